// round 10
// baseline (speedup 1.0000x reference)
#include <cuda_runtime.h>
#include <cuda_fp16.h>
#include <cstdint>

#define BATCH 2
#define SEQ 2048
#define NHEAD 16
#define HD 64
#define EMB 1024
#define ROWS (BATCH * SEQ)          // 4096
#define FDIM 192
#define NTOT (NHEAD * FDIM)         // 3072
#define QKV_ELEMS (BATCH * NHEAD * SEQ * HD)

// Scratch (no cudaMalloc allowed) — all fp16
__device__ __align__(1024) __half g_q[QKV_ELEMS];   // pre-scaled by 0.125*log2(e)
__device__ __align__(1024) __half g_k[QKV_ELEMS];
__device__ __align__(1024) __half g_v[QKV_ELEMS];
__device__ __align__(1024) __half g_xh[ROWS * EMB];
__device__ __align__(1024) __half g_wth[NTOT * EMB];   // W^T [h*192+f][1024]

// ---------------------------------------------------------------------------
// PTX helpers
// ---------------------------------------------------------------------------
__device__ __forceinline__ uint32_t smem_u32(const void* p) {
    uint32_t a;
    asm("{ .reg .u64 t; cvta.to.shared.u64 t, %1; cvt.u32.u64 %0, t; }" : "=r"(a) : "l"(p));
    return a;
}
__device__ __forceinline__ void cp16(uint32_t saddr, const void* gaddr) {
    asm volatile("cp.async.ca.shared.global [%0], [%1], 16;" :: "r"(saddr), "l"(gaddr));
}
__device__ __forceinline__ void cp_commit() {
    asm volatile("cp.async.commit_group;" ::: "memory");
}
template <int N>
__device__ __forceinline__ void cp_wait() {
    asm volatile("cp.async.wait_group %0;" :: "n"(N) : "memory");
}
__device__ __forceinline__ void ldmx4(uint32_t* r, uint32_t addr) {
    asm volatile("ldmatrix.sync.aligned.m8n8.x4.shared.b16 {%0,%1,%2,%3}, [%4];"
                 : "=r"(r[0]), "=r"(r[1]), "=r"(r[2]), "=r"(r[3]) : "r"(addr));
}
__device__ __forceinline__ void ldmx4t(uint32_t* r, uint32_t addr) {
    asm volatile("ldmatrix.sync.aligned.m8n8.x4.trans.shared.b16 {%0,%1,%2,%3}, [%4];"
                 : "=r"(r[0]), "=r"(r[1]), "=r"(r[2]), "=r"(r[3]) : "r"(addr));
}
__device__ __forceinline__ void mma_f16(float* c, const uint32_t* a, uint32_t b0, uint32_t b1) {
    asm volatile(
        "mma.sync.aligned.m16n8k16.row.col.f32.f16.f16.f32 "
        "{%0,%1,%2,%3}, {%4,%5,%6,%7}, {%8,%9}, {%0,%1,%2,%3};"
        : "+f"(c[0]), "+f"(c[1]), "+f"(c[2]), "+f"(c[3])
        : "r"(a[0]), "r"(a[1]), "r"(a[2]), "r"(a[3]), "r"(b0), "r"(b1));
}
__device__ __forceinline__ float ex2f(float x) {
    float y;
    asm("ex2.approx.f32 %0, %1;" : "=f"(y) : "f"(x));
    return y;
}
__device__ __forceinline__ __half2 h2ex2(__half2 x) {
    __half2 y;
    asm("ex2.approx.f16x2 %0, %1;" : "=r"(*(uint32_t*)&y) : "r"(*(uint32_t*)&x));
    return y;
}

// ---------------------------------------------------------------------------
// Merged prep: blocks [0,4096) round x to fp16; blocks [4096,7168) transpose W.
// ---------------------------------------------------------------------------
__global__ __launch_bounds__(256) void prep_kernel(const float4* __restrict__ x,
                                                   const float* __restrict__ W)
{
    if (blockIdx.x < 4096) {
        int i = blockIdx.x * 256 + threadIdx.x;
        float4 v = x[i];
        ((__half2*)g_xh)[2 * i + 0] = __floats2half2_rn(v.x, v.y);
        ((__half2*)g_xh)[2 * i + 1] = __floats2half2_rn(v.z, v.w);
    } else {
        __shared__ float t[32][33];
        int b = blockIdx.x - 4096;              // 3072 blocks
        int d0 = (b & 31) * 32;                 // 32 d-tiles
        int f0 = ((b >> 5) % 6) * 32;           // 6 f-tiles
        int h = b / 192;                        // 16 heads
        int xx = threadIdx.x & 31, yy = threadIdx.x >> 5;   // 32 x 8
        const float* Wh = W + (size_t)h * EMB * FDIM;
        #pragma unroll
        for (int j = 0; j < 32; j += 8)
            t[yy + j][xx] = Wh[(size_t)(d0 + yy + j) * FDIM + f0 + xx];
        __syncthreads();
        #pragma unroll
        for (int j = 0; j < 32; j += 8)
            g_wth[(size_t)(h * FDIM + f0 + yy + j) * EMB + d0 + xx] = __float2half(t[xx][yy + j]);
    }
}

// ---------------------------------------------------------------------------
// QKV GEMM fp16: C[4096, 3072] = xh @ Wt^T via mma.m16n8k16 + ldmatrix.
// CTA 128x128x64(h), 2-stage cp.async (72KB), 4 warps, 3 CTAs/SM.
// ---------------------------------------------------------------------------
static constexpr int CTA_M = 128;
static constexpr int CTA_N = 128;
static constexpr int CTA_K = 64;           // halves per stage
static constexpr int GST = 2;
static constexpr int LDAh = 72;            // halves; 144 B rows (9x16 -> CF ldmatrix)
static constexpr int A_H = CTA_M * LDAh;   // 9216
static constexpr int B_H = CTA_N * LDAh;   // 9216
static constexpr int STG_H = A_H + B_H;    // 18432
static constexpr int QKV_SMEM = GST * STG_H * 2;  // 73728 B
static constexpr int KIT = EMB / CTA_K;    // 16

__global__ __launch_bounds__(128, 3) void qkv_mma_kernel(const float* __restrict__ bias)
{
    extern __shared__ __half smh[];
    const int tid = threadIdx.x;
    const int wid = tid >> 5, lane = tid & 31;
    const int t4 = lane & 3, g = lane >> 2;
    const int rowBase = blockIdx.x * CTA_M;
    const int colBase = blockIdx.y * CTA_N;
    const int warp_m0 = (wid >> 1) * 64;
    const int warp_n0 = (wid & 1) * 64;

    const uint32_t sb = smem_u32(smh);
    const __half* gA = g_xh + (size_t)rowBase * EMB;
    const __half* gB = g_wth + (size_t)colBase * EMB;

    auto load_stage = [&](int s, int k0) {
        uint32_t As = sb + (s * STG_H) * 2;
        uint32_t Bs = As + A_H * 2;
        #pragma unroll
        for (int q = 0; q < 8; q++) {
            int c = tid + q * 128;
            int row = c >> 3, ch = (c & 7) * 8;
            cp16(As + (row * LDAh + ch) * 2, gA + (size_t)row * EMB + k0 + ch);
        }
        #pragma unroll
        for (int q = 0; q < 8; q++) {
            int c = tid + q * 128;
            int row = c >> 3, ch = (c & 7) * 8;
            cp16(Bs + (row * LDAh + ch) * 2, gB + (size_t)row * EMB + k0 + ch);
        }
    };

    float acc[4][8][4];
    #pragma unroll
    for (int i = 0; i < 4; i++)
        #pragma unroll
        for (int j = 0; j < 8; j++)
            #pragma unroll
            for (int r = 0; r < 4; r++) acc[i][j][r] = 0.f;

    load_stage(0, 0);
    cp_commit();
    load_stage(1, CTA_K);
    cp_commit();

    const int lrow16 = lane & 15;
    const int lcol8 = (lane >> 4) * 8;

    for (int it = 0; it < KIT; it++) {
        cp_wait<1>();
        __syncthreads();

        uint32_t As = sb + ((it & 1) * STG_H) * 2;
        uint32_t Bs = As + A_H * 2;

        #pragma unroll
        for (int kc = 0; kc < 4; kc++) {
            uint32_t a[4][4];
            #pragma unroll
            for (int mi = 0; mi < 4; mi++)
                ldmx4(a[mi], As + ((warp_m0 + mi * 16 + lrow16) * LDAh + kc * 16 + lcol8) * 2);
            #pragma unroll
            for (int np = 0; np < 4; np++) {
                uint32_t bf[4];
                ldmx4(bf, Bs + ((warp_n0 + np * 16 + lrow16) * LDAh + kc * 16 + lcol8) * 2);
                #pragma unroll
                for (int mi = 0; mi < 4; mi++) {
                    mma_f16(acc[mi][2 * np + 0], a[mi], bf[0], bf[2]);
                    mma_f16(acc[mi][2 * np + 1], a[mi], bf[1], bf[3]);
                }
            }
        }
        __syncthreads();
        if (it + 2 < KIT) load_stage(it & 1, (it + 2) * CTA_K);
        cp_commit();
    }

    const float QSC = 0.1803368801f;   // 0.125 * log2(e)
    #pragma unroll
    for (int mi = 0; mi < 4; mi++) {
        #pragma unroll
        for (int nj = 0; nj < 8; nj++) {
            int row0 = rowBase + warp_m0 + mi * 16 + g;
            int n = colBase + warp_n0 + nj * 8 + 2 * t4;
            int h = n / FDIM, f = n - h * FDIM;
            __half* dstbuf = (f < 64) ? g_k : ((f < 128) ? g_q : g_v);
            float sc = (f >= 64 && f < 128) ? QSC : 1.0f;
            int fd = f & 63;
            float2 bv = make_float2(bias[h * FDIM + f], bias[h * FDIM + f + 1]);
            #pragma unroll
            for (int half_ = 0; half_ < 2; half_++) {
                int r = row0 + half_ * 8;
                int b = r >> 11, ns = r & (SEQ - 1);
                __half2 ov = __floats2half2_rn((acc[mi][nj][half_ * 2 + 0] + bv.x) * sc,
                                               (acc[mi][nj][half_ * 2 + 1] + bv.y) * sc);
                *(__half2*)(dstbuf + (((size_t)(b * NHEAD + h)) * SEQ + ns) * HD + fd) = ov;
            }
        }
    }
}

// ---------------------------------------------------------------------------
// Causal flash attention fp16 (FA2). CTA: 128 queries, 8 warps x 16 rows.
// KV: 64-key double-buffered cp.async tiles (R7 config — best measured).
// f16x2 exp; P born packed. Per-warp diagonal block skip: only nva of 4
// 16-key blocks are computed on diagonal tiles (uniform per warp).
// ---------------------------------------------------------------------------
static constexpr int LDH = 72;                       // halves; 144 B rows
static constexpr int OFFQ = 0;                       // 128*72 halves
static constexpr int KVT_H = 64 * LDH;               // 4608 halves per K or V tile
static constexpr int OFFKV = 128 * LDH;              // stages: [K V][K V]
static constexpr int ATT_SMEM = (OFFKV + 4 * KVT_H) * 2;  // 55296 B

__global__ __launch_bounds__(256, 2) void attn_fa_kernel(float* __restrict__ out)
{
    extern __shared__ __half sh[];
    const int tid = threadIdx.x, wid = tid >> 5, lane = tid & 31;
    const int t4 = lane & 3, g = lane >> 2;
    const int qt = (int)gridDim.x - 1 - (int)blockIdx.x;  // heavy tiles first
    const int bh = blockIdx.y;
    const int qbase = qt * 128;

    const __half* Qg = g_q + (size_t)bh * SEQ * HD + (size_t)qbase * HD;
    const __half* Kg = g_k + (size_t)bh * SEQ * HD;
    const __half* Vg = g_v + (size_t)bh * SEQ * HD;

    const uint32_t sb = smem_u32(sh);

    // Q: 128 rows x 8 chunks(8h) -> 4 cp16 / thread  (group 0)
    #pragma unroll
    for (int q = 0; q < 4; q++) {
        int c = tid + q * 256;
        int row = c >> 3, ch = (c & 7) * 8;
        cp16(sb + (OFFQ + row * LDH + ch) * 2, Qg + (size_t)row * HD + ch);
    }
    cp_commit();

    auto load_kv = [&](int st, int jt) {
        uint32_t kb = sb + (OFFKV + st * 2 * KVT_H) * 2;
        const __half* kg = Kg + (size_t)jt * 64 * HD;
        const __half* vg = Vg + (size_t)jt * 64 * HD;
        #pragma unroll
        for (int q = 0; q < 2; q++) {
            int c = tid + q * 256;
            int row = c >> 3, ch = (c & 7) * 8;
            cp16(kb + (row * LDH + ch) * 2, kg + (size_t)row * HD + ch);
            cp16(kb + (KVT_H + row * LDH + ch) * 2, vg + (size_t)row * HD + ch);
        }
    };

    load_kv(0, 0);
    cp_commit();
    cp_wait<1>();           // Q group done
    __syncthreads();

    const int lrow16 = lane & 15;
    const int lcol8 = (lane >> 4) * 8;
    uint32_t qf[4][4];
    #pragma unroll
    for (int kc = 0; kc < 4; kc++)
        ldmx4(qf[kc], sb + (OFFQ + (wid * 16 + lrow16) * LDH + kc * 16 + lcol8) * 2);

    float oacc[8][4];
    #pragma unroll
    for (int j = 0; j < 8; j++)
        #pragma unroll
        for (int r = 0; r < 4; r++) oacc[j][r] = 0.f;
    float mrow[2] = {-1e30f, -1e30f};
    float lrow[2] = {0.f, 0.f};

    const int wrmin = qbase + wid * 16;
    const int wrmax = wrmin + 15;
    const int ntiles = 2 * qt + 2;

    const int v_row = ((lane >> 4) << 3) + (lane & 7);
    const int v_col = ((lane >> 3) & 1) * 8;

    for (int jt = 0; jt < ntiles; jt++) {
        if (jt + 1 < ntiles) load_kv((jt + 1) & 1, jt + 1);
        cp_commit();
        cp_wait<1>();
        __syncthreads();

        const int kb0 = jt * 64;
        uint32_t Ks = sb + (OFFKV + (jt & 1) * 2 * KVT_H) * 2;
        uint32_t Vs = Ks + KVT_H * 2;

        if (kb0 <= wrmax) {
            // nva: number of valid 16-key blocks for this warp (uniform per warp)
            const int nva = min(4, ((wrmax - kb0) >> 4) + 1);

            // ---- S = Q @ K^T (only valid blocks) ----
            float sacc[8][4];
            #pragma unroll
            for (int j = 0; j < 8; j++)
                #pragma unroll
                for (int r = 0; r < 4; r++) sacc[j][r] = 0.f;

            #pragma unroll
            for (int np = 0; np < 4; np++) {
                if (np < nva) {
                    #pragma unroll
                    for (int kc = 0; kc < 4; kc++) {
                        uint32_t bf[4];
                        ldmx4(bf, Ks + ((np * 16 + lrow16) * LDH + kc * 16 + lcol8) * 2);
                        mma_f16(sacc[2 * np + 0], qf[kc], bf[0], bf[2]);
                        mma_f16(sacc[2 * np + 1], qf[kc], bf[1], bf[3]);
                    }
                }
            }

            // ---- causal mask (diagonal region only, valid blocks only) ----
            if (kb0 + 63 > wrmin) {
                #pragma unroll
                for (int nf = 0; nf < 8; nf++) {
                    if (nf < 2 * nva) {
                        int key = kb0 + nf * 8 + 2 * t4;
                        #pragma unroll
                        for (int r = 0; r < 2; r++) {
                            int qrow = wrmin + r * 8 + g;
                            if (key > qrow)     sacc[nf][r * 2 + 0] = -1e30f;
                            if (key + 1 > qrow) sacc[nf][r * 2 + 1] = -1e30f;
                        }
                    }
                }
            }

            // ---- rowmax (fp32) + alpha ----
            float alpha[2], mn2[2];
            #pragma unroll
            for (int r = 0; r < 2; r++) {
                float mx = fmaxf(sacc[0][r * 2], sacc[0][r * 2 + 1]);
                #pragma unroll
                for (int nf = 1; nf < 8; nf++)
                    if (nf < 2 * nva)
                        mx = fmaxf(mx, fmaxf(sacc[nf][r * 2], sacc[nf][r * 2 + 1]));
                mx = fmaxf(mx, __shfl_xor_sync(0xffffffffu, mx, 1));
                mx = fmaxf(mx, __shfl_xor_sync(0xffffffffu, mx, 2));
                float mn = fmaxf(mrow[r], mx);
                alpha[r] = ex2f(mrow[r] - mn);
                mrow[r] = mn;
                mn2[r] = mn;
            }

            // ---- exp in f16x2 (P born packed; only valid blocks) ----
            __half2 ph2[8][2];
            #pragma unroll
            for (int nf = 0; nf < 8; nf++)
                #pragma unroll
                for (int r = 0; r < 2; r++)
                    if (nf < 2 * nva)
                        ph2[nf][r] = h2ex2(__floats2half2_rn(sacc[nf][r * 2 + 0] - mn2[r],
                                                             sacc[nf][r * 2 + 1] - mn2[r]));

            // ---- row sum: hadd2 pairs (valid blocks) then f32 ----
            #pragma unroll
            for (int r = 0; r < 2; r++) {
                __half2 q01 = __hadd2(ph2[0][r], ph2[1][r]);
                float2 f0 = __half22float2(q01);
                float rs = f0.x + f0.y;
                if (nva > 1) {
                    float2 f1 = __half22float2(__hadd2(ph2[2][r], ph2[3][r]));
                    rs += f1.x + f1.y;
                }
                if (nva > 2) {
                    float2 f2 = __half22float2(__hadd2(ph2[4][r], ph2[5][r]));
                    rs += f2.x + f2.y;
                }
                if (nva > 3) {
                    float2 f3 = __half22float2(__hadd2(ph2[6][r], ph2[7][r]));
                    rs += f3.x + f3.y;
                }
                rs += __shfl_xor_sync(0xffffffffu, rs, 1);
                rs += __shfl_xor_sync(0xffffffffu, rs, 2);
                lrow[r] = lrow[r] * alpha[r] + rs;
            }

            // ---- O rescale ----
            #pragma unroll
            for (int nf = 0; nf < 8; nf++) {
                oacc[nf][0] *= alpha[0]; oacc[nf][1] *= alpha[0];
                oacc[nf][2] *= alpha[1]; oacc[nf][3] *= alpha[1];
            }

            // ---- O += P @ V (only valid 16-key chunks) ----
            #pragma unroll
            for (int kc2 = 0; kc2 < 4; kc2++) {
                if (kc2 < nva) {
                    uint32_t a[4] = {*(uint32_t*)&ph2[2 * kc2][0],     *(uint32_t*)&ph2[2 * kc2][1],
                                     *(uint32_t*)&ph2[2 * kc2 + 1][0], *(uint32_t*)&ph2[2 * kc2 + 1][1]};
                    #pragma unroll
                    for (int np = 0; np < 4; np++) {
                        uint32_t bf[4];
                        ldmx4t(bf, Vs + ((kc2 * 16 + v_row) * LDH + np * 16 + v_col) * 2);
                        mma_f16(oacc[2 * np + 0], a, bf[0], bf[2]);
                        mma_f16(oacc[2 * np + 1], a, bf[1], bf[3]);
                    }
                }
            }
        }
        __syncthreads();   // all warps done reading before buffer reuse
    }

    // ---- epilogue ----
    const int b = bh >> 4, h = bh & (NHEAD - 1);
    #pragma unroll
    for (int r = 0; r < 2; r++) {
        int qrow = qbase + wid * 16 + r * 8 + g;
        float inv = 1.0f / lrow[r];
        float* op = out + ((size_t)(b * SEQ + qrow)) * EMB + h * HD;
        #pragma unroll
        for (int nf = 0; nf < 8; nf++) {
            float2 ov = make_float2(oacc[nf][r * 2] * inv, oacc[nf][r * 2 + 1] * inv);
            *(float2*)(op + nf * 8 + 2 * t4) = ov;
        }
    }
}

// ---------------------------------------------------------------------------
// Host launcher
// ---------------------------------------------------------------------------
extern "C" void kernel_launch(void* const* d_in, const int* in_sizes, int n_in,
                              void* d_out, int out_size)
{
    const float* x    = (const float*)d_in[0];  // [2,2048,1024]
    const float* W    = (const float*)d_in[1];  // [16,1024,192]
    const float* bias = (const float*)d_in[2];  // [16,192]
    float* out = (float*)d_out;                 // [2,2048,1024]

    prep_kernel<<<4096 + 3072, 256>>>((const float4*)x, W);

    static bool smem_set = false;
    if (!smem_set) {
        cudaFuncSetAttribute(qkv_mma_kernel, cudaFuncAttributeMaxDynamicSharedMemorySize, QKV_SMEM);
        cudaFuncSetAttribute(attn_fa_kernel, cudaFuncAttributeMaxDynamicSharedMemorySize, ATT_SMEM);
        smem_set = true;
    }
    qkv_mma_kernel<<<dim3(ROWS / CTA_M, NTOT / CTA_N), 128, QKV_SMEM>>>(bias);

    attn_fa_kernel<<<dim3(SEQ / 128, BATCH * NHEAD), 256, ATT_SMEM>>>(out);
}

// round 11
// speedup vs baseline: 1.0805x; 1.0805x over previous
#include <cuda_runtime.h>
#include <cuda_fp16.h>
#include <cstdint>

#define BATCH 2
#define SEQ 2048
#define NHEAD 16
#define HD 64
#define EMB 1024
#define ROWS (BATCH * SEQ)          // 4096
#define FDIM 192
#define NTOT (NHEAD * FDIM)         // 3072
#define QKV_ELEMS (BATCH * NHEAD * SEQ * HD)

// Scratch (no cudaMalloc allowed) — all fp16
__device__ __align__(1024) __half g_q[QKV_ELEMS];   // pre-scaled by 0.125*log2(e)
__device__ __align__(1024) __half g_k[QKV_ELEMS];
__device__ __align__(1024) __half g_v[QKV_ELEMS];
__device__ __align__(1024) __half g_xh[ROWS * EMB];
__device__ __align__(1024) __half g_wth[NTOT * EMB];   // W^T [h*192+f][1024]

// ---------------------------------------------------------------------------
// PTX helpers
// ---------------------------------------------------------------------------
__device__ __forceinline__ uint32_t smem_u32(const void* p) {
    uint32_t a;
    asm("{ .reg .u64 t; cvta.to.shared.u64 t, %1; cvt.u32.u64 %0, t; }" : "=r"(a) : "l"(p));
    return a;
}
__device__ __forceinline__ void cp16(uint32_t saddr, const void* gaddr) {
    asm volatile("cp.async.ca.shared.global [%0], [%1], 16;" :: "r"(saddr), "l"(gaddr));
}
__device__ __forceinline__ void cp_commit() {
    asm volatile("cp.async.commit_group;" ::: "memory");
}
template <int N>
__device__ __forceinline__ void cp_wait() {
    asm volatile("cp.async.wait_group %0;" :: "n"(N) : "memory");
}
__device__ __forceinline__ void ldmx4(uint32_t* r, uint32_t addr) {
    asm volatile("ldmatrix.sync.aligned.m8n8.x4.shared.b16 {%0,%1,%2,%3}, [%4];"
                 : "=r"(r[0]), "=r"(r[1]), "=r"(r[2]), "=r"(r[3]) : "r"(addr));
}
__device__ __forceinline__ void ldmx4t(uint32_t* r, uint32_t addr) {
    asm volatile("ldmatrix.sync.aligned.m8n8.x4.trans.shared.b16 {%0,%1,%2,%3}, [%4];"
                 : "=r"(r[0]), "=r"(r[1]), "=r"(r[2]), "=r"(r[3]) : "r"(addr));
}
__device__ __forceinline__ void mma_f16(float* c, const uint32_t* a, uint32_t b0, uint32_t b1) {
    asm volatile(
        "mma.sync.aligned.m16n8k16.row.col.f32.f16.f16.f32 "
        "{%0,%1,%2,%3}, {%4,%5,%6,%7}, {%8,%9}, {%0,%1,%2,%3};"
        : "+f"(c[0]), "+f"(c[1]), "+f"(c[2]), "+f"(c[3])
        : "r"(a[0]), "r"(a[1]), "r"(a[2]), "r"(a[3]), "r"(b0), "r"(b1));
}
__device__ __forceinline__ float ex2f(float x) {
    float y;
    asm("ex2.approx.f32 %0, %1;" : "=f"(y) : "f"(x));
    return y;
}
__device__ __forceinline__ __half2 h2ex2(__half2 x) {
    __half2 y;
    asm("ex2.approx.f16x2 %0, %1;" : "=r"(*(uint32_t*)&y) : "r"(*(uint32_t*)&x));
    return y;
}

// ---------------------------------------------------------------------------
// Merged prep: blocks [0,4096) round x to fp16; blocks [4096,7168) transpose W.
// ---------------------------------------------------------------------------
__global__ __launch_bounds__(256) void prep_kernel(const float4* __restrict__ x,
                                                   const float* __restrict__ W)
{
    if (blockIdx.x < 4096) {
        int i = blockIdx.x * 256 + threadIdx.x;
        float4 v = x[i];
        ((__half2*)g_xh)[2 * i + 0] = __floats2half2_rn(v.x, v.y);
        ((__half2*)g_xh)[2 * i + 1] = __floats2half2_rn(v.z, v.w);
    } else {
        __shared__ float t[32][33];
        int b = blockIdx.x - 4096;              // 3072 blocks
        int d0 = (b & 31) * 32;                 // 32 d-tiles
        int f0 = ((b >> 5) % 6) * 32;           // 6 f-tiles
        int h = b / 192;                        // 16 heads
        int xx = threadIdx.x & 31, yy = threadIdx.x >> 5;   // 32 x 8
        const float* Wh = W + (size_t)h * EMB * FDIM;
        #pragma unroll
        for (int j = 0; j < 32; j += 8)
            t[yy + j][xx] = Wh[(size_t)(d0 + yy + j) * FDIM + f0 + xx];
        __syncthreads();
        #pragma unroll
        for (int j = 0; j < 32; j += 8)
            g_wth[(size_t)(h * FDIM + f0 + yy + j) * EMB + d0 + xx] = __float2half(t[xx][yy + j]);
    }
}

// ---------------------------------------------------------------------------
// QKV GEMM fp16: C[4096, 3072] = xh @ Wt^T via mma.m16n8k16 + ldmatrix.
// CTA 128x128x64(h), 2-stage cp.async (72KB), 4 warps, 3 CTAs/SM.
// ---------------------------------------------------------------------------
static constexpr int CTA_M = 128;
static constexpr int CTA_N = 128;
static constexpr int CTA_K = 64;           // halves per stage
static constexpr int GST = 2;
static constexpr int LDAh = 72;            // halves; 144 B rows (9x16 -> CF ldmatrix)
static constexpr int A_H = CTA_M * LDAh;   // 9216
static constexpr int B_H = CTA_N * LDAh;   // 9216
static constexpr int STG_H = A_H + B_H;    // 18432
static constexpr int QKV_SMEM = GST * STG_H * 2;  // 73728 B
static constexpr int KIT = EMB / CTA_K;    // 16

__global__ __launch_bounds__(128, 3) void qkv_mma_kernel(const float* __restrict__ bias)
{
    extern __shared__ __half smh[];
    const int tid = threadIdx.x;
    const int wid = tid >> 5, lane = tid & 31;
    const int t4 = lane & 3, g = lane >> 2;
    const int rowBase = blockIdx.x * CTA_M;
    const int colBase = blockIdx.y * CTA_N;
    const int warp_m0 = (wid >> 1) * 64;
    const int warp_n0 = (wid & 1) * 64;

    const uint32_t sb = smem_u32(smh);
    const __half* gA = g_xh + (size_t)rowBase * EMB;
    const __half* gB = g_wth + (size_t)colBase * EMB;

    auto load_stage = [&](int s, int k0) {
        uint32_t As = sb + (s * STG_H) * 2;
        uint32_t Bs = As + A_H * 2;
        #pragma unroll
        for (int q = 0; q < 8; q++) {
            int c = tid + q * 128;
            int row = c >> 3, ch = (c & 7) * 8;
            cp16(As + (row * LDAh + ch) * 2, gA + (size_t)row * EMB + k0 + ch);
        }
        #pragma unroll
        for (int q = 0; q < 8; q++) {
            int c = tid + q * 128;
            int row = c >> 3, ch = (c & 7) * 8;
            cp16(Bs + (row * LDAh + ch) * 2, gB + (size_t)row * EMB + k0 + ch);
        }
    };

    float acc[4][8][4];
    #pragma unroll
    for (int i = 0; i < 4; i++)
        #pragma unroll
        for (int j = 0; j < 8; j++)
            #pragma unroll
            for (int r = 0; r < 4; r++) acc[i][j][r] = 0.f;

    load_stage(0, 0);
    cp_commit();
    load_stage(1, CTA_K);
    cp_commit();

    const int lrow16 = lane & 15;
    const int lcol8 = (lane >> 4) * 8;

    for (int it = 0; it < KIT; it++) {
        cp_wait<1>();
        __syncthreads();

        uint32_t As = sb + ((it & 1) * STG_H) * 2;
        uint32_t Bs = As + A_H * 2;

        #pragma unroll
        for (int kc = 0; kc < 4; kc++) {
            uint32_t a[4][4];
            #pragma unroll
            for (int mi = 0; mi < 4; mi++)
                ldmx4(a[mi], As + ((warp_m0 + mi * 16 + lrow16) * LDAh + kc * 16 + lcol8) * 2);
            #pragma unroll
            for (int np = 0; np < 4; np++) {
                uint32_t bf[4];
                ldmx4(bf, Bs + ((warp_n0 + np * 16 + lrow16) * LDAh + kc * 16 + lcol8) * 2);
                #pragma unroll
                for (int mi = 0; mi < 4; mi++) {
                    mma_f16(acc[mi][2 * np + 0], a[mi], bf[0], bf[2]);
                    mma_f16(acc[mi][2 * np + 1], a[mi], bf[1], bf[3]);
                }
            }
        }
        __syncthreads();
        if (it + 2 < KIT) load_stage(it & 1, (it + 2) * CTA_K);
        cp_commit();
    }

    const float QSC = 0.1803368801f;   // 0.125 * log2(e)
    #pragma unroll
    for (int mi = 0; mi < 4; mi++) {
        #pragma unroll
        for (int nj = 0; nj < 8; nj++) {
            int row0 = rowBase + warp_m0 + mi * 16 + g;
            int n = colBase + warp_n0 + nj * 8 + 2 * t4;
            int h = n / FDIM, f = n - h * FDIM;
            __half* dstbuf = (f < 64) ? g_k : ((f < 128) ? g_q : g_v);
            float sc = (f >= 64 && f < 128) ? QSC : 1.0f;
            int fd = f & 63;
            float2 bv = make_float2(bias[h * FDIM + f], bias[h * FDIM + f + 1]);
            #pragma unroll
            for (int half_ = 0; half_ < 2; half_++) {
                int r = row0 + half_ * 8;
                int b = r >> 11, ns = r & (SEQ - 1);
                __half2 ov = __floats2half2_rn((acc[mi][nj][half_ * 2 + 0] + bv.x) * sc,
                                               (acc[mi][nj][half_ * 2 + 1] + bv.y) * sc);
                *(__half2*)(dstbuf + (((size_t)(b * NHEAD + h)) * SEQ + ns) * HD + fd) = ov;
            }
        }
    }
}

// ---------------------------------------------------------------------------
// Causal flash attention fp16 (FA2) — R7-exact config (best measured: 85us).
// CTA: 128 queries, 8 warps x 16 rows. KV: 64-key double-buffered cp.async
// tiles. Merged 64-key softmax, f16x2 exp, P born packed.
// ---------------------------------------------------------------------------
static constexpr int LDH = 72;                       // halves; 144 B rows
static constexpr int OFFQ = 0;
static constexpr int KVT_H = 64 * LDH;               // 4608 halves per K or V tile
static constexpr int OFFKV = 128 * LDH;
static constexpr int ATT_SMEM = (OFFKV + 4 * KVT_H) * 2;  // 55296 B

__global__ __launch_bounds__(256, 2) void attn_fa_kernel(float* __restrict__ out)
{
    extern __shared__ __half sh[];
    const int tid = threadIdx.x, wid = tid >> 5, lane = tid & 31;
    const int t4 = lane & 3, g = lane >> 2;
    const int qt = (int)gridDim.x - 1 - (int)blockIdx.x;  // heavy tiles first
    const int bh = blockIdx.y;
    const int qbase = qt * 128;

    const __half* Qg = g_q + (size_t)bh * SEQ * HD + (size_t)qbase * HD;
    const __half* Kg = g_k + (size_t)bh * SEQ * HD;
    const __half* Vg = g_v + (size_t)bh * SEQ * HD;

    const uint32_t sb = smem_u32(sh);

    #pragma unroll
    for (int q = 0; q < 4; q++) {
        int c = tid + q * 256;
        int row = c >> 3, ch = (c & 7) * 8;
        cp16(sb + (OFFQ + row * LDH + ch) * 2, Qg + (size_t)row * HD + ch);
    }
    cp_commit();

    auto load_kv = [&](int st, int jt) {
        uint32_t kb = sb + (OFFKV + st * 2 * KVT_H) * 2;
        const __half* kg = Kg + (size_t)jt * 64 * HD;
        const __half* vg = Vg + (size_t)jt * 64 * HD;
        #pragma unroll
        for (int q = 0; q < 2; q++) {
            int c = tid + q * 256;
            int row = c >> 3, ch = (c & 7) * 8;
            cp16(kb + (row * LDH + ch) * 2, kg + (size_t)row * HD + ch);
            cp16(kb + (KVT_H + row * LDH + ch) * 2, vg + (size_t)row * HD + ch);
        }
    };

    load_kv(0, 0);
    cp_commit();
    cp_wait<1>();           // Q group done
    __syncthreads();

    const int lrow16 = lane & 15;
    const int lcol8 = (lane >> 4) * 8;
    uint32_t qf[4][4];
    #pragma unroll
    for (int kc = 0; kc < 4; kc++)
        ldmx4(qf[kc], sb + (OFFQ + (wid * 16 + lrow16) * LDH + kc * 16 + lcol8) * 2);

    float oacc[8][4];
    #pragma unroll
    for (int j = 0; j < 8; j++)
        #pragma unroll
        for (int r = 0; r < 4; r++) oacc[j][r] = 0.f;
    float mrow[2] = {-1e30f, -1e30f};
    float lrow[2] = {0.f, 0.f};

    const int wrmin = qbase + wid * 16;
    const int wrmax = wrmin + 15;
    const int ntiles = 2 * qt + 2;

    const int v_row = ((lane >> 4) << 3) + (lane & 7);
    const int v_col = ((lane >> 3) & 1) * 8;

    for (int jt = 0; jt < ntiles; jt++) {
        if (jt + 1 < ntiles) load_kv((jt + 1) & 1, jt + 1);
        cp_commit();
        cp_wait<1>();
        __syncthreads();

        const int kb0 = jt * 64;
        uint32_t Ks = sb + (OFFKV + (jt & 1) * 2 * KVT_H) * 2;
        uint32_t Vs = Ks + KVT_H * 2;

        if (kb0 <= wrmax) {
            // ---- S = Q @ K^T (64 keys) ----
            float sacc[8][4];
            #pragma unroll
            for (int j = 0; j < 8; j++)
                #pragma unroll
                for (int r = 0; r < 4; r++) sacc[j][r] = 0.f;

            #pragma unroll
            for (int kc = 0; kc < 4; kc++) {
                #pragma unroll
                for (int np = 0; np < 4; np++) {
                    uint32_t bf[4];
                    ldmx4(bf, Ks + ((np * 16 + lrow16) * LDH + kc * 16 + lcol8) * 2);
                    mma_f16(sacc[2 * np + 0], qf[kc], bf[0], bf[2]);
                    mma_f16(sacc[2 * np + 1], qf[kc], bf[1], bf[3]);
                }
            }

            // ---- causal mask (diagonal region only) ----
            if (kb0 + 63 > wrmin) {
                #pragma unroll
                for (int nf = 0; nf < 8; nf++) {
                    int key = kb0 + nf * 8 + 2 * t4;
                    #pragma unroll
                    for (int r = 0; r < 2; r++) {
                        int qrow = wrmin + r * 8 + g;
                        if (key > qrow)     sacc[nf][r * 2 + 0] = -1e30f;
                        if (key + 1 > qrow) sacc[nf][r * 2 + 1] = -1e30f;
                    }
                }
            }

            // ---- rowmax (fp32) + alpha ----
            float alpha[2], mn2[2];
            #pragma unroll
            for (int r = 0; r < 2; r++) {
                float mx = fmaxf(sacc[0][r * 2], sacc[0][r * 2 + 1]);
                #pragma unroll
                for (int nf = 1; nf < 8; nf++)
                    mx = fmaxf(mx, fmaxf(sacc[nf][r * 2], sacc[nf][r * 2 + 1]));
                mx = fmaxf(mx, __shfl_xor_sync(0xffffffffu, mx, 1));
                mx = fmaxf(mx, __shfl_xor_sync(0xffffffffu, mx, 2));
                float mn = fmaxf(mrow[r], mx);
                alpha[r] = ex2f(mrow[r] - mn);
                mrow[r] = mn;
                mn2[r] = mn;
            }

            // ---- exp in f16x2 (P born packed) ----
            __half2 ph2[8][2];
            #pragma unroll
            for (int nf = 0; nf < 8; nf++)
                #pragma unroll
                for (int r = 0; r < 2; r++)
                    ph2[nf][r] = h2ex2(__floats2half2_rn(sacc[nf][r * 2 + 0] - mn2[r],
                                                         sacc[nf][r * 2 + 1] - mn2[r]));

            // ---- row sum: hadd2 pairs then f32 ----
            #pragma unroll
            for (int r = 0; r < 2; r++) {
                __half2 q01 = __hadd2(ph2[0][r], ph2[1][r]);
                __half2 q23 = __hadd2(ph2[2][r], ph2[3][r]);
                __half2 q45 = __hadd2(ph2[4][r], ph2[5][r]);
                __half2 q67 = __hadd2(ph2[6][r], ph2[7][r]);
                float2 f0 = __half22float2(q01);
                float2 f1 = __half22float2(q23);
                float2 f2 = __half22float2(q45);
                float2 f3 = __half22float2(q67);
                float rs = ((f0.x + f0.y) + (f1.x + f1.y)) + ((f2.x + f2.y) + (f3.x + f3.y));
                rs += __shfl_xor_sync(0xffffffffu, rs, 1);
                rs += __shfl_xor_sync(0xffffffffu, rs, 2);
                lrow[r] = lrow[r] * alpha[r] + rs;
            }

            // ---- O rescale ----
            #pragma unroll
            for (int nf = 0; nf < 8; nf++) {
                oacc[nf][0] *= alpha[0]; oacc[nf][1] *= alpha[0];
                oacc[nf][2] *= alpha[1]; oacc[nf][3] *= alpha[1];
            }

            // ---- O += P @ V ----
            #pragma unroll
            for (int kc2 = 0; kc2 < 4; kc2++) {
                uint32_t a[4] = {*(uint32_t*)&ph2[2 * kc2][0],     *(uint32_t*)&ph2[2 * kc2][1],
                                 *(uint32_t*)&ph2[2 * kc2 + 1][0], *(uint32_t*)&ph2[2 * kc2 + 1][1]};
                #pragma unroll
                for (int np = 0; np < 4; np++) {
                    uint32_t bf[4];
                    ldmx4t(bf, Vs + ((kc2 * 16 + v_row) * LDH + np * 16 + v_col) * 2);
                    mma_f16(oacc[2 * np + 0], a, bf[0], bf[2]);
                    mma_f16(oacc[2 * np + 1], a, bf[1], bf[3]);
                }
            }
        }
        __syncthreads();
    }

    // ---- epilogue ----
    const int b = bh >> 4, h = bh & (NHEAD - 1);
    #pragma unroll
    for (int r = 0; r < 2; r++) {
        int qrow = qbase + wid * 16 + r * 8 + g;
        float inv = 1.0f / lrow[r];
        float* op = out + ((size_t)(b * SEQ + qrow)) * EMB + h * HD;
        #pragma unroll
        for (int nf = 0; nf < 8; nf++) {
            float2 ov = make_float2(oacc[nf][r * 2] * inv, oacc[nf][r * 2 + 1] * inv);
            *(float2*)(op + nf * 8 + 2 * t4) = ov;
        }
    }
}

// ---------------------------------------------------------------------------
// Host launcher
// ---------------------------------------------------------------------------
extern "C" void kernel_launch(void* const* d_in, const int* in_sizes, int n_in,
                              void* d_out, int out_size)
{
    const float* x    = (const float*)d_in[0];  // [2,2048,1024]
    const float* W    = (const float*)d_in[1];  // [16,1024,192]
    const float* bias = (const float*)d_in[2];  // [16,192]
    float* out = (float*)d_out;                 // [2,2048,1024]

    prep_kernel<<<4096 + 3072, 256>>>((const float4*)x, W);

    static bool smem_set = false;
    if (!smem_set) {
        cudaFuncSetAttribute(qkv_mma_kernel, cudaFuncAttributeMaxDynamicSharedMemorySize, QKV_SMEM);
        cudaFuncSetAttribute(attn_fa_kernel, cudaFuncAttributeMaxDynamicSharedMemorySize, ATT_SMEM);
        smem_set = true;
    }
    qkv_mma_kernel<<<dim3(ROWS / CTA_M, NTOT / CTA_N), 128, QKV_SMEM>>>(bias);

    attn_fa_kernel<<<dim3(SEQ / 128, BATCH * NHEAD), 256, ATT_SMEM>>>(out);
}

// round 12
// speedup vs baseline: 1.1897x; 1.1011x over previous
#include <cuda_runtime.h>
#include <cuda_fp16.h>
#include <cstdint>

#define BATCH 2
#define SEQ 2048
#define NHEAD 16
#define HD 64
#define EMB 1024
#define ROWS (BATCH * SEQ)          // 4096
#define FDIM 192
#define NTOT (NHEAD * FDIM)         // 3072
#define QKV_ELEMS (BATCH * NHEAD * SEQ * HD)

// Scratch (no cudaMalloc allowed) — all fp16
__device__ __align__(1024) __half g_q[QKV_ELEMS];   // pre-scaled by 0.125*log2(e)
__device__ __align__(1024) __half g_k[QKV_ELEMS];
__device__ __align__(1024) __half g_v[QKV_ELEMS];
__device__ __align__(1024) __half g_xh[ROWS * EMB];
__device__ __align__(1024) __half g_wth[NTOT * EMB];   // W^T [h*192+f][1024]

// ---------------------------------------------------------------------------
// PTX helpers
// ---------------------------------------------------------------------------
__device__ __forceinline__ uint32_t smem_u32(const void* p) {
    uint32_t a;
    asm("{ .reg .u64 t; cvta.to.shared.u64 t, %1; cvt.u32.u64 %0, t; }" : "=r"(a) : "l"(p));
    return a;
}
__device__ __forceinline__ void cp16(uint32_t saddr, const void* gaddr) {
    asm volatile("cp.async.ca.shared.global [%0], [%1], 16;" :: "r"(saddr), "l"(gaddr));
}
__device__ __forceinline__ void cp_commit() {
    asm volatile("cp.async.commit_group;" ::: "memory");
}
template <int N>
__device__ __forceinline__ void cp_wait() {
    asm volatile("cp.async.wait_group %0;" :: "n"(N) : "memory");
}
__device__ __forceinline__ void ldmx4(uint32_t* r, uint32_t addr) {
    asm volatile("ldmatrix.sync.aligned.m8n8.x4.shared.b16 {%0,%1,%2,%3}, [%4];"
                 : "=r"(r[0]), "=r"(r[1]), "=r"(r[2]), "=r"(r[3]) : "r"(addr));
}
__device__ __forceinline__ void ldmx4t(uint32_t* r, uint32_t addr) {
    asm volatile("ldmatrix.sync.aligned.m8n8.x4.trans.shared.b16 {%0,%1,%2,%3}, [%4];"
                 : "=r"(r[0]), "=r"(r[1]), "=r"(r[2]), "=r"(r[3]) : "r"(addr));
}
__device__ __forceinline__ void mma_f16(float* c, const uint32_t* a, uint32_t b0, uint32_t b1) {
    asm volatile(
        "mma.sync.aligned.m16n8k16.row.col.f32.f16.f16.f32 "
        "{%0,%1,%2,%3}, {%4,%5,%6,%7}, {%8,%9}, {%0,%1,%2,%3};"
        : "+f"(c[0]), "+f"(c[1]), "+f"(c[2]), "+f"(c[3])
        : "r"(a[0]), "r"(a[1]), "r"(a[2]), "r"(a[3]), "r"(b0), "r"(b1));
}
__device__ __forceinline__ float ex2f(float x) {
    float y;
    asm("ex2.approx.f32 %0, %1;" : "=f"(y) : "f"(x));
    return y;
}
__device__ __forceinline__ __half2 h2ex2(__half2 x) {
    __half2 y;
    asm("ex2.approx.f16x2 %0, %1;" : "=r"(*(uint32_t*)&y) : "r"(*(uint32_t*)&x));
    return y;
}

// ---------------------------------------------------------------------------
// Merged prep: blocks [0,4096) round x to fp16; blocks [4096,7168) transpose W.
// ---------------------------------------------------------------------------
__global__ __launch_bounds__(256) void prep_kernel(const float4* __restrict__ x,
                                                   const float* __restrict__ W)
{
    if (blockIdx.x < 4096) {
        int i = blockIdx.x * 256 + threadIdx.x;
        float4 v = x[i];
        ((__half2*)g_xh)[2 * i + 0] = __floats2half2_rn(v.x, v.y);
        ((__half2*)g_xh)[2 * i + 1] = __floats2half2_rn(v.z, v.w);
    } else {
        __shared__ float t[32][33];
        int b = blockIdx.x - 4096;              // 3072 blocks
        int d0 = (b & 31) * 32;                 // 32 d-tiles
        int f0 = ((b >> 5) % 6) * 32;           // 6 f-tiles
        int h = b / 192;                        // 16 heads
        int xx = threadIdx.x & 31, yy = threadIdx.x >> 5;   // 32 x 8
        const float* Wh = W + (size_t)h * EMB * FDIM;
        #pragma unroll
        for (int j = 0; j < 32; j += 8)
            t[yy + j][xx] = Wh[(size_t)(d0 + yy + j) * FDIM + f0 + xx];
        __syncthreads();
        #pragma unroll
        for (int j = 0; j < 32; j += 8)
            g_wth[(size_t)(h * FDIM + f0 + yy + j) * EMB + d0 + xx] = __float2half(t[xx][yy + j]);
    }
}

// ---------------------------------------------------------------------------
// QKV GEMM fp16: C[4096, 3072] = xh @ Wt^T via mma.m16n8k16 + ldmatrix.
// CTA 128x128x64(h), 2-stage cp.async (72KB), 4 warps, 3 CTAs/SM.
// ---------------------------------------------------------------------------
static constexpr int CTA_M = 128;
static constexpr int CTA_N = 128;
static constexpr int CTA_K = 64;           // halves per stage
static constexpr int GST = 2;
static constexpr int LDAh = 72;            // halves; 144 B rows (9x16 -> CF ldmatrix)
static constexpr int A_H = CTA_M * LDAh;   // 9216
static constexpr int B_H = CTA_N * LDAh;   // 9216
static constexpr int STG_H = A_H + B_H;    // 18432
static constexpr int QKV_SMEM = GST * STG_H * 2;  // 73728 B
static constexpr int KIT = EMB / CTA_K;    // 16

__global__ __launch_bounds__(128, 3) void qkv_mma_kernel(const float* __restrict__ bias)
{
    extern __shared__ __half smh[];
    const int tid = threadIdx.x;
    const int wid = tid >> 5, lane = tid & 31;
    const int t4 = lane & 3, g = lane >> 2;
    const int rowBase = blockIdx.x * CTA_M;
    const int colBase = blockIdx.y * CTA_N;
    const int warp_m0 = (wid >> 1) * 64;
    const int warp_n0 = (wid & 1) * 64;

    const uint32_t sb = smem_u32(smh);
    const __half* gA = g_xh + (size_t)rowBase * EMB;
    const __half* gB = g_wth + (size_t)colBase * EMB;

    auto load_stage = [&](int s, int k0) {
        uint32_t As = sb + (s * STG_H) * 2;
        uint32_t Bs = As + A_H * 2;
        #pragma unroll
        for (int q = 0; q < 8; q++) {
            int c = tid + q * 128;
            int row = c >> 3, ch = (c & 7) * 8;
            cp16(As + (row * LDAh + ch) * 2, gA + (size_t)row * EMB + k0 + ch);
        }
        #pragma unroll
        for (int q = 0; q < 8; q++) {
            int c = tid + q * 128;
            int row = c >> 3, ch = (c & 7) * 8;
            cp16(Bs + (row * LDAh + ch) * 2, gB + (size_t)row * EMB + k0 + ch);
        }
    };

    float acc[4][8][4];
    #pragma unroll
    for (int i = 0; i < 4; i++)
        #pragma unroll
        for (int j = 0; j < 8; j++)
            #pragma unroll
            for (int r = 0; r < 4; r++) acc[i][j][r] = 0.f;

    load_stage(0, 0);
    cp_commit();
    load_stage(1, CTA_K);
    cp_commit();

    const int lrow16 = lane & 15;
    const int lcol8 = (lane >> 4) * 8;

    for (int it = 0; it < KIT; it++) {
        cp_wait<1>();
        __syncthreads();

        uint32_t As = sb + ((it & 1) * STG_H) * 2;
        uint32_t Bs = As + A_H * 2;

        #pragma unroll
        for (int kc = 0; kc < 4; kc++) {
            uint32_t a[4][4];
            #pragma unroll
            for (int mi = 0; mi < 4; mi++)
                ldmx4(a[mi], As + ((warp_m0 + mi * 16 + lrow16) * LDAh + kc * 16 + lcol8) * 2);
            #pragma unroll
            for (int np = 0; np < 4; np++) {
                uint32_t bf[4];
                ldmx4(bf, Bs + ((warp_n0 + np * 16 + lrow16) * LDAh + kc * 16 + lcol8) * 2);
                #pragma unroll
                for (int mi = 0; mi < 4; mi++) {
                    mma_f16(acc[mi][2 * np + 0], a[mi], bf[0], bf[2]);
                    mma_f16(acc[mi][2 * np + 1], a[mi], bf[1], bf[3]);
                }
            }
        }
        __syncthreads();
        if (it + 2 < KIT) load_stage(it & 1, (it + 2) * CTA_K);
        cp_commit();
    }

    const float QSC = 0.1803368801f;   // 0.125 * log2(e)
    #pragma unroll
    for (int mi = 0; mi < 4; mi++) {
        #pragma unroll
        for (int nj = 0; nj < 8; nj++) {
            int row0 = rowBase + warp_m0 + mi * 16 + g;
            int n = colBase + warp_n0 + nj * 8 + 2 * t4;
            int h = n / FDIM, f = n - h * FDIM;
            __half* dstbuf = (f < 64) ? g_k : ((f < 128) ? g_q : g_v);
            float sc = (f >= 64 && f < 128) ? QSC : 1.0f;
            int fd = f & 63;
            float2 bv = make_float2(bias[h * FDIM + f], bias[h * FDIM + f + 1]);
            #pragma unroll
            for (int half_ = 0; half_ < 2; half_++) {
                int r = row0 + half_ * 8;
                int b = r >> 11, ns = r & (SEQ - 1);
                __half2 ov = __floats2half2_rn((acc[mi][nj][half_ * 2 + 0] + bv.x) * sc,
                                               (acc[mi][nj][half_ * 2 + 1] + bv.y) * sc);
                *(__half2*)(dstbuf + (((size_t)(b * NHEAD + h)) * SEQ + ns) * HD + fd) = ov;
            }
        }
    }
}

// ---------------------------------------------------------------------------
// Causal flash attention fp16 (FA2), R7 inner loops. Work-paired scheduling:
// grid (8, 32) = 256 CTAs (single wave); each CTA runs TWO q-tiles — heavy
// qt = 15-bx, then light qt = bx — so per-CTA work is uniform (17 batches).
// ---------------------------------------------------------------------------
static constexpr int LDH = 72;                       // halves; 144 B rows
static constexpr int OFFQ = 0;
static constexpr int KVT_H = 64 * LDH;               // 4608 halves per K or V tile
static constexpr int OFFKV = 128 * LDH;
static constexpr int ATT_SMEM = (OFFKV + 4 * KVT_H) * 2;  // 55296 B

__global__ __launch_bounds__(256, 2) void attn_fa_kernel(float* __restrict__ out)
{
    extern __shared__ __half sh[];
    const int tid = threadIdx.x, wid = tid >> 5, lane = tid & 31;
    const int t4 = lane & 3, g = lane >> 2;
    const int bx = blockIdx.x;                      // 0..7
    const int bh = blockIdx.y;
    const int nqt = (int)gridDim.x * 2;             // 16 q-tiles

    const __half* Kg = g_k + (size_t)bh * SEQ * HD;
    const __half* Vg = g_v + (size_t)bh * SEQ * HD;

    const uint32_t sb = smem_u32(sh);
    const int lrow16 = lane & 15;
    const int lcol8 = (lane >> 4) * 8;
    const int v_row = ((lane >> 4) << 3) + (lane & 7);
    const int v_col = ((lane >> 3) & 1) * 8;
    const int b = bh >> 4, h = bh & (NHEAD - 1);

    auto load_kv = [&](int st, int jt) {
        uint32_t kb = sb + (OFFKV + st * 2 * KVT_H) * 2;
        const __half* kg = Kg + (size_t)jt * 64 * HD;
        const __half* vg = Vg + (size_t)jt * 64 * HD;
        #pragma unroll
        for (int q = 0; q < 2; q++) {
            int c = tid + q * 256;
            int row = c >> 3, ch = (c & 7) * 8;
            cp16(kb + (row * LDH + ch) * 2, kg + (size_t)row * HD + ch);
            cp16(kb + (KVT_H + row * LDH + ch) * 2, vg + (size_t)row * HD + ch);
        }
    };

    #pragma unroll 1
    for (int pass = 0; pass < 2; pass++) {
        const int qt = pass ? bx : (nqt - 1 - bx);
        const int qbase = qt * 128;
        const __half* Qg = g_q + (size_t)bh * SEQ * HD + (size_t)qbase * HD;

        // Q: 128 rows x 8 chunks(8h) -> 4 cp16 / thread  (group)
        #pragma unroll
        for (int q = 0; q < 4; q++) {
            int c = tid + q * 256;
            int row = c >> 3, ch = (c & 7) * 8;
            cp16(sb + (OFFQ + row * LDH + ch) * 2, Qg + (size_t)row * HD + ch);
        }
        cp_commit();

        load_kv(0, 0);
        cp_commit();
        cp_wait<1>();           // Q group done
        __syncthreads();

        uint32_t qf[4][4];
        #pragma unroll
        for (int kc = 0; kc < 4; kc++)
            ldmx4(qf[kc], sb + (OFFQ + (wid * 16 + lrow16) * LDH + kc * 16 + lcol8) * 2);

        float oacc[8][4];
        #pragma unroll
        for (int j = 0; j < 8; j++)
            #pragma unroll
            for (int r = 0; r < 4; r++) oacc[j][r] = 0.f;
        float mrow[2] = {-1e30f, -1e30f};
        float lrow[2] = {0.f, 0.f};

        const int wrmin = qbase + wid * 16;
        const int wrmax = wrmin + 15;
        const int ntiles = 2 * qt + 2;

        for (int jt = 0; jt < ntiles; jt++) {
            if (jt + 1 < ntiles) load_kv((jt + 1) & 1, jt + 1);
            cp_commit();
            cp_wait<1>();
            __syncthreads();

            const int kb0 = jt * 64;
            uint32_t Ks = sb + (OFFKV + (jt & 1) * 2 * KVT_H) * 2;
            uint32_t Vs = Ks + KVT_H * 2;

            if (kb0 <= wrmax) {
                // ---- S = Q @ K^T (64 keys) ----
                float sacc[8][4];
                #pragma unroll
                for (int j = 0; j < 8; j++)
                    #pragma unroll
                    for (int r = 0; r < 4; r++) sacc[j][r] = 0.f;

                #pragma unroll
                for (int kc = 0; kc < 4; kc++) {
                    #pragma unroll
                    for (int np = 0; np < 4; np++) {
                        uint32_t bf[4];
                        ldmx4(bf, Ks + ((np * 16 + lrow16) * LDH + kc * 16 + lcol8) * 2);
                        mma_f16(sacc[2 * np + 0], qf[kc], bf[0], bf[2]);
                        mma_f16(sacc[2 * np + 1], qf[kc], bf[1], bf[3]);
                    }
                }

                // ---- causal mask (diagonal region only) ----
                if (kb0 + 63 > wrmin) {
                    #pragma unroll
                    for (int nf = 0; nf < 8; nf++) {
                        int key = kb0 + nf * 8 + 2 * t4;
                        #pragma unroll
                        for (int r = 0; r < 2; r++) {
                            int qrow = wrmin + r * 8 + g;
                            if (key > qrow)     sacc[nf][r * 2 + 0] = -1e30f;
                            if (key + 1 > qrow) sacc[nf][r * 2 + 1] = -1e30f;
                        }
                    }
                }

                // ---- rowmax (fp32) + alpha ----
                float alpha[2], mn2[2];
                #pragma unroll
                for (int r = 0; r < 2; r++) {
                    float mx = fmaxf(sacc[0][r * 2], sacc[0][r * 2 + 1]);
                    #pragma unroll
                    for (int nf = 1; nf < 8; nf++)
                        mx = fmaxf(mx, fmaxf(sacc[nf][r * 2], sacc[nf][r * 2 + 1]));
                    mx = fmaxf(mx, __shfl_xor_sync(0xffffffffu, mx, 1));
                    mx = fmaxf(mx, __shfl_xor_sync(0xffffffffu, mx, 2));
                    float mn = fmaxf(mrow[r], mx);
                    alpha[r] = ex2f(mrow[r] - mn);
                    mrow[r] = mn;
                    mn2[r] = mn;
                }

                // ---- exp in f16x2 (P born packed) ----
                __half2 ph2[8][2];
                #pragma unroll
                for (int nf = 0; nf < 8; nf++)
                    #pragma unroll
                    for (int r = 0; r < 2; r++)
                        ph2[nf][r] = h2ex2(__floats2half2_rn(sacc[nf][r * 2 + 0] - mn2[r],
                                                             sacc[nf][r * 2 + 1] - mn2[r]));

                // ---- row sum: hadd2 pairs then f32 ----
                #pragma unroll
                for (int r = 0; r < 2; r++) {
                    __half2 q01 = __hadd2(ph2[0][r], ph2[1][r]);
                    __half2 q23 = __hadd2(ph2[2][r], ph2[3][r]);
                    __half2 q45 = __hadd2(ph2[4][r], ph2[5][r]);
                    __half2 q67 = __hadd2(ph2[6][r], ph2[7][r]);
                    float2 f0 = __half22float2(q01);
                    float2 f1 = __half22float2(q23);
                    float2 f2 = __half22float2(q45);
                    float2 f3 = __half22float2(q67);
                    float rs = ((f0.x + f0.y) + (f1.x + f1.y)) + ((f2.x + f2.y) + (f3.x + f3.y));
                    rs += __shfl_xor_sync(0xffffffffu, rs, 1);
                    rs += __shfl_xor_sync(0xffffffffu, rs, 2);
                    lrow[r] = lrow[r] * alpha[r] + rs;
                }

                // ---- O rescale ----
                #pragma unroll
                for (int nf = 0; nf < 8; nf++) {
                    oacc[nf][0] *= alpha[0]; oacc[nf][1] *= alpha[0];
                    oacc[nf][2] *= alpha[1]; oacc[nf][3] *= alpha[1];
                }

                // ---- O += P @ V ----
                #pragma unroll
                for (int kc2 = 0; kc2 < 4; kc2++) {
                    uint32_t a[4] = {*(uint32_t*)&ph2[2 * kc2][0],     *(uint32_t*)&ph2[2 * kc2][1],
                                     *(uint32_t*)&ph2[2 * kc2 + 1][0], *(uint32_t*)&ph2[2 * kc2 + 1][1]};
                    #pragma unroll
                    for (int np = 0; np < 4; np++) {
                        uint32_t bf[4];
                        ldmx4t(bf, Vs + ((kc2 * 16 + v_row) * LDH + np * 16 + v_col) * 2);
                        mma_f16(oacc[2 * np + 0], a, bf[0], bf[2]);
                        mma_f16(oacc[2 * np + 1], a, bf[1], bf[3]);
                    }
                }
            }
            __syncthreads();
        }

        // ---- epilogue for this pass ----
        #pragma unroll
        for (int r = 0; r < 2; r++) {
            int qrow = qbase + wid * 16 + r * 8 + g;
            float inv = 1.0f / lrow[r];
            float* op = out + ((size_t)(b * SEQ + qrow)) * EMB + h * HD;
            #pragma unroll
            for (int nf = 0; nf < 8; nf++) {
                float2 ov = make_float2(oacc[nf][r * 2] * inv, oacc[nf][r * 2 + 1] * inv);
                *(float2*)(op + nf * 8 + 2 * t4) = ov;
            }
        }
        __syncthreads();   // smem buffers idle before next pass reuses them
    }
}

// ---------------------------------------------------------------------------
// Host launcher
// ---------------------------------------------------------------------------
extern "C" void kernel_launch(void* const* d_in, const int* in_sizes, int n_in,
                              void* d_out, int out_size)
{
    const float* x    = (const float*)d_in[0];  // [2,2048,1024]
    const float* W    = (const float*)d_in[1];  // [16,1024,192]
    const float* bias = (const float*)d_in[2];  // [16,192]
    float* out = (float*)d_out;                 // [2,2048,1024]

    prep_kernel<<<4096 + 3072, 256>>>((const float4*)x, W);

    static bool smem_set = false;
    if (!smem_set) {
        cudaFuncSetAttribute(qkv_mma_kernel, cudaFuncAttributeMaxDynamicSharedMemorySize, QKV_SMEM);
        cudaFuncSetAttribute(attn_fa_kernel, cudaFuncAttributeMaxDynamicSharedMemorySize, ATT_SMEM);
        smem_set = true;
    }
    qkv_mma_kernel<<<dim3(ROWS / CTA_M, NTOT / CTA_N), 128, QKV_SMEM>>>(bias);

    attn_fa_kernel<<<dim3(SEQ / 256, BATCH * NHEAD), 256, ATT_SMEM>>>(out);
}

// round 14
// speedup vs baseline: 1.2373x; 1.0400x over previous
#include <cuda_runtime.h>
#include <cuda_fp16.h>
#include <cstdint>

#define BATCH 2
#define SEQ 2048
#define NHEAD 16
#define HD 64
#define EMB 1024
#define ROWS (BATCH * SEQ)          // 4096
#define FDIM 192
#define NTOT (NHEAD * FDIM)         // 3072
#define QKV_ELEMS (BATCH * NHEAD * SEQ * HD)

// Scratch (no cudaMalloc allowed) — all fp16
__device__ __align__(1024) __half g_q[QKV_ELEMS];   // pre-scaled by 0.125*log2(e)
__device__ __align__(1024) __half g_k[QKV_ELEMS];
__device__ __align__(1024) __half g_v[QKV_ELEMS];
__device__ __align__(1024) __half g_xh[ROWS * EMB];
__device__ __align__(1024) __half g_wth[NTOT * EMB];   // W^T [h*192+f][1024]

// ---------------------------------------------------------------------------
// PTX helpers
// ---------------------------------------------------------------------------
__device__ __forceinline__ uint32_t smem_u32(const void* p) {
    uint32_t a;
    asm("{ .reg .u64 t; cvta.to.shared.u64 t, %1; cvt.u32.u64 %0, t; }" : "=r"(a) : "l"(p));
    return a;
}
__device__ __forceinline__ void cp16(uint32_t saddr, const void* gaddr) {
    asm volatile("cp.async.ca.shared.global [%0], [%1], 16;" :: "r"(saddr), "l"(gaddr));
}
__device__ __forceinline__ void cp_commit() {
    asm volatile("cp.async.commit_group;" ::: "memory");
}
template <int N>
__device__ __forceinline__ void cp_wait() {
    asm volatile("cp.async.wait_group %0;" :: "n"(N) : "memory");
}
__device__ __forceinline__ void ldmx4(uint32_t* r, uint32_t addr) {
    asm volatile("ldmatrix.sync.aligned.m8n8.x4.shared.b16 {%0,%1,%2,%3}, [%4];"
                 : "=r"(r[0]), "=r"(r[1]), "=r"(r[2]), "=r"(r[3]) : "r"(addr));
}
__device__ __forceinline__ void ldmx4t(uint32_t* r, uint32_t addr) {
    asm volatile("ldmatrix.sync.aligned.m8n8.x4.trans.shared.b16 {%0,%1,%2,%3}, [%4];"
                 : "=r"(r[0]), "=r"(r[1]), "=r"(r[2]), "=r"(r[3]) : "r"(addr));
}
__device__ __forceinline__ void mma_f16(float* c, const uint32_t* a, uint32_t b0, uint32_t b1) {
    asm volatile(
        "mma.sync.aligned.m16n8k16.row.col.f32.f16.f16.f32 "
        "{%0,%1,%2,%3}, {%4,%5,%6,%7}, {%8,%9}, {%0,%1,%2,%3};"
        : "+f"(c[0]), "+f"(c[1]), "+f"(c[2]), "+f"(c[3])
        : "r"(a[0]), "r"(a[1]), "r"(a[2]), "r"(a[3]), "r"(b0), "r"(b1));
}
__device__ __forceinline__ float ex2f(float x) {
    float y;
    asm("ex2.approx.f32 %0, %1;" : "=f"(y) : "f"(x));
    return y;
}
__device__ __forceinline__ __half2 h2ex2(__half2 x) {
    __half2 y;
    asm("ex2.approx.f16x2 %0, %1;" : "=r"(*(uint32_t*)&y) : "r"(*(uint32_t*)&x));
    return y;
}

// ---------------------------------------------------------------------------
// Merged prep: blocks [0,4096) round x to fp16; blocks [4096,7168) transpose W.
// ---------------------------------------------------------------------------
__global__ __launch_bounds__(256) void prep_kernel(const float4* __restrict__ x,
                                                   const float* __restrict__ W)
{
    if (blockIdx.x < 4096) {
        int i = blockIdx.x * 256 + threadIdx.x;
        float4 v = x[i];
        ((__half2*)g_xh)[2 * i + 0] = __floats2half2_rn(v.x, v.y);
        ((__half2*)g_xh)[2 * i + 1] = __floats2half2_rn(v.z, v.w);
    } else {
        __shared__ float t[32][33];
        int b = blockIdx.x - 4096;              // 3072 blocks
        int d0 = (b & 31) * 32;                 // 32 d-tiles
        int f0 = ((b >> 5) % 6) * 32;           // 6 f-tiles
        int h = b / 192;                        // 16 heads
        int xx = threadIdx.x & 31, yy = threadIdx.x >> 5;   // 32 x 8
        const float* Wh = W + (size_t)h * EMB * FDIM;
        #pragma unroll
        for (int j = 0; j < 32; j += 8)
            t[yy + j][xx] = Wh[(size_t)(d0 + yy + j) * FDIM + f0 + xx];
        __syncthreads();
        #pragma unroll
        for (int j = 0; j < 32; j += 8)
            g_wth[(size_t)(h * FDIM + f0 + yy + j) * EMB + d0 + xx] = __float2half(t[xx][yy + j]);
    }
}

// ---------------------------------------------------------------------------
// QKV GEMM fp16: C[4096, 3072] = xh @ Wt^T via mma.m16n8k16 + ldmatrix.
// CTA 128x128x64(h), 2-stage cp.async (72KB), 4 warps, 3 CTAs/SM.
// ---------------------------------------------------------------------------
static constexpr int CTA_M = 128;
static constexpr int CTA_N = 128;
static constexpr int CTA_K = 64;           // halves per stage
static constexpr int GST = 2;
static constexpr int LDAh = 72;            // halves; 144 B rows (9x16 -> CF ldmatrix)
static constexpr int A_H = CTA_M * LDAh;   // 9216
static constexpr int B_H = CTA_N * LDAh;   // 9216
static constexpr int STG_H = A_H + B_H;    // 18432
static constexpr int QKV_SMEM = GST * STG_H * 2;  // 73728 B
static constexpr int KIT = EMB / CTA_K;    // 16

__global__ __launch_bounds__(128, 3) void qkv_mma_kernel(const float* __restrict__ bias)
{
    extern __shared__ __half smh[];
    const int tid = threadIdx.x;
    const int wid = tid >> 5, lane = tid & 31;
    const int t4 = lane & 3, g = lane >> 2;
    const int rowBase = blockIdx.x * CTA_M;
    const int colBase = blockIdx.y * CTA_N;
    const int warp_m0 = (wid >> 1) * 64;
    const int warp_n0 = (wid & 1) * 64;

    const uint32_t sb = smem_u32(smh);
    const __half* gA = g_xh + (size_t)rowBase * EMB;
    const __half* gB = g_wth + (size_t)colBase * EMB;

    auto load_stage = [&](int s, int k0) {
        uint32_t As = sb + (s * STG_H) * 2;
        uint32_t Bs = As + A_H * 2;
        #pragma unroll
        for (int q = 0; q < 8; q++) {
            int c = tid + q * 128;
            int row = c >> 3, ch = (c & 7) * 8;
            cp16(As + (row * LDAh + ch) * 2, gA + (size_t)row * EMB + k0 + ch);
        }
        #pragma unroll
        for (int q = 0; q < 8; q++) {
            int c = tid + q * 128;
            int row = c >> 3, ch = (c & 7) * 8;
            cp16(Bs + (row * LDAh + ch) * 2, gB + (size_t)row * EMB + k0 + ch);
        }
    };

    float acc[4][8][4];
    #pragma unroll
    for (int i = 0; i < 4; i++)
        #pragma unroll
        for (int j = 0; j < 8; j++)
            #pragma unroll
            for (int r = 0; r < 4; r++) acc[i][j][r] = 0.f;

    load_stage(0, 0);
    cp_commit();
    load_stage(1, CTA_K);
    cp_commit();

    const int lrow16 = lane & 15;
    const int lcol8 = (lane >> 4) * 8;

    for (int it = 0; it < KIT; it++) {
        cp_wait<1>();
        __syncthreads();

        uint32_t As = sb + ((it & 1) * STG_H) * 2;
        uint32_t Bs = As + A_H * 2;

        #pragma unroll
        for (int kc = 0; kc < 4; kc++) {
            uint32_t a[4][4];
            #pragma unroll
            for (int mi = 0; mi < 4; mi++)
                ldmx4(a[mi], As + ((warp_m0 + mi * 16 + lrow16) * LDAh + kc * 16 + lcol8) * 2);
            #pragma unroll
            for (int np = 0; np < 4; np++) {
                uint32_t bf[4];
                ldmx4(bf, Bs + ((warp_n0 + np * 16 + lrow16) * LDAh + kc * 16 + lcol8) * 2);
                #pragma unroll
                for (int mi = 0; mi < 4; mi++) {
                    mma_f16(acc[mi][2 * np + 0], a[mi], bf[0], bf[2]);
                    mma_f16(acc[mi][2 * np + 1], a[mi], bf[1], bf[3]);
                }
            }
        }
        __syncthreads();
        if (it + 2 < KIT) load_stage(it & 1, (it + 2) * CTA_K);
        cp_commit();
    }

    const float QSC = 0.1803368801f;   // 0.125 * log2(e)
    #pragma unroll
    for (int mi = 0; mi < 4; mi++) {
        #pragma unroll
        for (int nj = 0; nj < 8; nj++) {
            int row0 = rowBase + warp_m0 + mi * 16 + g;
            int n = colBase + warp_n0 + nj * 8 + 2 * t4;
            int h = n / FDIM, f = n - h * FDIM;
            __half* dstbuf = (f < 64) ? g_k : ((f < 128) ? g_q : g_v);
            float sc = (f >= 64 && f < 128) ? QSC : 1.0f;
            int fd = f & 63;
            float2 bv = make_float2(bias[h * FDIM + f], bias[h * FDIM + f + 1]);
            #pragma unroll
            for (int half_ = 0; half_ < 2; half_++) {
                int r = row0 + half_ * 8;
                int b = r >> 11, ns = r & (SEQ - 1);
                __half2 ov = __floats2half2_rn((acc[mi][nj][half_ * 2 + 0] + bv.x) * sc,
                                               (acc[mi][nj][half_ * 2 + 1] + bv.y) * sc);
                *(__half2*)(dstbuf + (((size_t)(b * NHEAD + h)) * SEQ + ns) * HD + fd) = ov;
            }
        }
    }
}

// ---------------------------------------------------------------------------
// Causal flash attention fp16 (FA2), R12 inner loops. LPT-balanced schedule:
// 512 work items (qt, bh); item j: qt = 15 - j/32 (descending cost), bh = j&31.
// Grid = 296 CTAs = exactly 2 per SM. CTA i runs item i (pass 0), then item
// 591 - i (pass 1; valid when 591-i < 512, i.e. i >= 80).
// Per-CTA cost in [14,16] units; per-SM 28-32 (vs R12 makespan 34).
// ---------------------------------------------------------------------------
static constexpr int LDH = 72;                       // halves; 144 B rows
static constexpr int OFFQ = 0;
static constexpr int KVT_H = 64 * LDH;               // 4608 halves per K or V tile
static constexpr int OFFKV = 128 * LDH;
static constexpr int ATT_SMEM = (OFFKV + 4 * KVT_H) * 2;  // 55296 B
static constexpr int ATT_GRID = 296;                 // 2 x 148 SMs
static constexpr int NITEMS = 512;                   // 16 qt x 32 bh
static constexpr int PAIR_SUM = NITEMS - 1 + (ATT_GRID - (NITEMS - ATT_GRID));  // 591

__global__ __launch_bounds__(256, 2) void attn_fa_kernel(float* __restrict__ out)
{
    extern __shared__ __half sh[];
    const int tid = threadIdx.x, wid = tid >> 5, lane = tid & 31;
    const int t4 = lane & 3, g = lane >> 2;
    const int cta = blockIdx.x;                      // 0..295

    const uint32_t sb = smem_u32(sh);
    const int lrow16 = lane & 15;
    const int lcol8 = (lane >> 4) * 8;
    const int v_row = ((lane >> 4) << 3) + (lane & 7);
    const int v_col = ((lane >> 3) & 1) * 8;

    #pragma unroll 1
    for (int pass = 0; pass < 2; pass++) {
        const int j = pass ? (PAIR_SUM - cta) : cta;   // 591 - cta on pass 1
        if (j >= NITEMS) continue;     // pass 1 invalid for cta < 80

        const int qt = 15 - (j >> 5);
        const int bh = j & 31;
        const int qbase = qt * 128;

        const __half* Qg = g_q + (size_t)bh * SEQ * HD + (size_t)qbase * HD;
        const __half* Kg = g_k + (size_t)bh * SEQ * HD;
        const __half* Vg = g_v + (size_t)bh * SEQ * HD;

        // Q: 128 rows x 8 chunks(8h) -> 4 cp16 / thread  (group)
        #pragma unroll
        for (int q = 0; q < 4; q++) {
            int c = tid + q * 256;
            int row = c >> 3, ch = (c & 7) * 8;
            cp16(sb + (OFFQ + row * LDH + ch) * 2, Qg + (size_t)row * HD + ch);
        }
        cp_commit();

        auto load_kv = [&](int st, int jt) {
            uint32_t kb = sb + (OFFKV + st * 2 * KVT_H) * 2;
            const __half* kg = Kg + (size_t)jt * 64 * HD;
            const __half* vg = Vg + (size_t)jt * 64 * HD;
            #pragma unroll
            for (int q = 0; q < 2; q++) {
                int c = tid + q * 256;
                int row = c >> 3, ch = (c & 7) * 8;
                cp16(kb + (row * LDH + ch) * 2, kg + (size_t)row * HD + ch);
                cp16(kb + (KVT_H + row * LDH + ch) * 2, vg + (size_t)row * HD + ch);
            }
        };

        load_kv(0, 0);
        cp_commit();
        cp_wait<1>();           // Q group done
        __syncthreads();

        uint32_t qf[4][4];
        #pragma unroll
        for (int kc = 0; kc < 4; kc++)
            ldmx4(qf[kc], sb + (OFFQ + (wid * 16 + lrow16) * LDH + kc * 16 + lcol8) * 2);

        float oacc[8][4];
        #pragma unroll
        for (int jj = 0; jj < 8; jj++)
            #pragma unroll
            for (int r = 0; r < 4; r++) oacc[jj][r] = 0.f;
        float mrow[2] = {-1e30f, -1e30f};
        float lrow[2] = {0.f, 0.f};

        const int wrmin = qbase + wid * 16;
        const int wrmax = wrmin + 15;
        const int ntiles = 2 * qt + 2;

        for (int jt = 0; jt < ntiles; jt++) {
            if (jt + 1 < ntiles) load_kv((jt + 1) & 1, jt + 1);
            cp_commit();
            cp_wait<1>();
            __syncthreads();

            const int kb0 = jt * 64;
            uint32_t Ks = sb + (OFFKV + (jt & 1) * 2 * KVT_H) * 2;
            uint32_t Vs = Ks + KVT_H * 2;

            if (kb0 <= wrmax) {
                // ---- S = Q @ K^T (64 keys) ----
                float sacc[8][4];
                #pragma unroll
                for (int jj = 0; jj < 8; jj++)
                    #pragma unroll
                    for (int r = 0; r < 4; r++) sacc[jj][r] = 0.f;

                #pragma unroll
                for (int kc = 0; kc < 4; kc++) {
                    #pragma unroll
                    for (int np = 0; np < 4; np++) {
                        uint32_t bf[4];
                        ldmx4(bf, Ks + ((np * 16 + lrow16) * LDH + kc * 16 + lcol8) * 2);
                        mma_f16(sacc[2 * np + 0], qf[kc], bf[0], bf[2]);
                        mma_f16(sacc[2 * np + 1], qf[kc], bf[1], bf[3]);
                    }
                }

                // ---- causal mask (diagonal region only) ----
                if (kb0 + 63 > wrmin) {
                    #pragma unroll
                    for (int nf = 0; nf < 8; nf++) {
                        int key = kb0 + nf * 8 + 2 * t4;
                        #pragma unroll
                        for (int r = 0; r < 2; r++) {
                            int qrow = wrmin + r * 8 + g;
                            if (key > qrow)     sacc[nf][r * 2 + 0] = -1e30f;
                            if (key + 1 > qrow) sacc[nf][r * 2 + 1] = -1e30f;
                        }
                    }
                }

                // ---- rowmax (fp32) + alpha ----
                float alpha[2], mn2[2];
                #pragma unroll
                for (int r = 0; r < 2; r++) {
                    float mx = fmaxf(sacc[0][r * 2], sacc[0][r * 2 + 1]);
                    #pragma unroll
                    for (int nf = 1; nf < 8; nf++)
                        mx = fmaxf(mx, fmaxf(sacc[nf][r * 2], sacc[nf][r * 2 + 1]));
                    mx = fmaxf(mx, __shfl_xor_sync(0xffffffffu, mx, 1));
                    mx = fmaxf(mx, __shfl_xor_sync(0xffffffffu, mx, 2));
                    float mn = fmaxf(mrow[r], mx);
                    alpha[r] = ex2f(mrow[r] - mn);
                    mrow[r] = mn;
                    mn2[r] = mn;
                }

                // ---- exp in f16x2 (P born packed) ----
                __half2 ph2[8][2];
                #pragma unroll
                for (int nf = 0; nf < 8; nf++)
                    #pragma unroll
                    for (int r = 0; r < 2; r++)
                        ph2[nf][r] = h2ex2(__floats2half2_rn(sacc[nf][r * 2 + 0] - mn2[r],
                                                             sacc[nf][r * 2 + 1] - mn2[r]));

                // ---- row sum: hadd2 pairs then f32 ----
                #pragma unroll
                for (int r = 0; r < 2; r++) {
                    __half2 q01 = __hadd2(ph2[0][r], ph2[1][r]);
                    __half2 q23 = __hadd2(ph2[2][r], ph2[3][r]);
                    __half2 q45 = __hadd2(ph2[4][r], ph2[5][r]);
                    __half2 q67 = __hadd2(ph2[6][r], ph2[7][r]);
                    float2 f0 = __half22float2(q01);
                    float2 f1 = __half22float2(q23);
                    float2 f2 = __half22float2(q45);
                    float2 f3 = __half22float2(q67);
                    float rs = ((f0.x + f0.y) + (f1.x + f1.y)) + ((f2.x + f2.y) + (f3.x + f3.y));
                    rs += __shfl_xor_sync(0xffffffffu, rs, 1);
                    rs += __shfl_xor_sync(0xffffffffu, rs, 2);
                    lrow[r] = lrow[r] * alpha[r] + rs;
                }

                // ---- O rescale ----
                #pragma unroll
                for (int nf = 0; nf < 8; nf++) {
                    oacc[nf][0] *= alpha[0]; oacc[nf][1] *= alpha[0];
                    oacc[nf][2] *= alpha[1]; oacc[nf][3] *= alpha[1];
                }

                // ---- O += P @ V ----
                #pragma unroll
                for (int kc2 = 0; kc2 < 4; kc2++) {
                    uint32_t a[4] = {*(uint32_t*)&ph2[2 * kc2][0],     *(uint32_t*)&ph2[2 * kc2][1],
                                     *(uint32_t*)&ph2[2 * kc2 + 1][0], *(uint32_t*)&ph2[2 * kc2 + 1][1]};
                    #pragma unroll
                    for (int np = 0; np < 4; np++) {
                        uint32_t bf[4];
                        ldmx4t(bf, Vs + ((kc2 * 16 + v_row) * LDH + np * 16 + v_col) * 2);
                        mma_f16(oacc[2 * np + 0], a, bf[0], bf[2]);
                        mma_f16(oacc[2 * np + 1], a, bf[1], bf[3]);
                    }
                }
            }
            __syncthreads();
        }

        // ---- epilogue for this item ----
        const int b = bh >> 4, h = bh & (NHEAD - 1);
        #pragma unroll
        for (int r = 0; r < 2; r++) {
            int qrow = qbase + wid * 16 + r * 8 + g;
            float inv = 1.0f / lrow[r];
            float* op = out + ((size_t)(b * SEQ + qrow)) * EMB + h * HD;
            #pragma unroll
            for (int nf = 0; nf < 8; nf++) {
                float2 ov = make_float2(oacc[nf][r * 2] * inv, oacc[nf][r * 2 + 1] * inv);
                *(float2*)(op + nf * 8 + 2 * t4) = ov;
            }
        }
        __syncthreads();   // smem buffers idle before next item reuses them
    }
}

// ---------------------------------------------------------------------------
// Host launcher
// ---------------------------------------------------------------------------
extern "C" void kernel_launch(void* const* d_in, const int* in_sizes, int n_in,
                              void* d_out, int out_size)
{
    const float* x    = (const float*)d_in[0];  // [2,2048,1024]
    const float* W    = (const float*)d_in[1];  // [16,1024,192]
    const float* bias = (const float*)d_in[2];  // [16,192]
    float* out = (float*)d_out;                 // [2,2048,1024]

    prep_kernel<<<4096 + 3072, 256>>>((const float4*)x, W);

    static bool smem_set = false;
    if (!smem_set) {
        cudaFuncSetAttribute(qkv_mma_kernel, cudaFuncAttributeMaxDynamicSharedMemorySize, QKV_SMEM);
        cudaFuncSetAttribute(attn_fa_kernel, cudaFuncAttributeMaxDynamicSharedMemorySize, ATT_SMEM);
        smem_set = true;
    }
    qkv_mma_kernel<<<dim3(ROWS / CTA_M, NTOT / CTA_N), 128, QKV_SMEM>>>(bias);

    attn_fa_kernel<<<ATT_GRID, 256, ATT_SMEM>>>(out);
}

// round 15
// speedup vs baseline: 1.2505x; 1.0107x over previous
#include <cuda_runtime.h>
#include <cuda_fp16.h>
#include <cstdint>

#define BATCH 2
#define SEQ 2048
#define NHEAD 16
#define HD 64
#define EMB 1024
#define ROWS (BATCH * SEQ)          // 4096
#define FDIM 192
#define NTOT (NHEAD * FDIM)         // 3072
#define QKV_ELEMS (BATCH * NHEAD * SEQ * HD)

// Scratch (no cudaMalloc allowed) — all fp16
__device__ __align__(1024) __half g_q[QKV_ELEMS];   // pre-scaled by 0.125*log2(e)
__device__ __align__(1024) __half g_k[QKV_ELEMS];
__device__ __align__(1024) __half g_v[QKV_ELEMS];
__device__ __align__(1024) __half g_xh[ROWS * EMB];
__device__ __align__(1024) __half g_wth[NTOT * EMB];   // W^T [h*192+f][1024]

// ---------------------------------------------------------------------------
// PTX helpers
// ---------------------------------------------------------------------------
__device__ __forceinline__ uint32_t smem_u32(const void* p) {
    uint32_t a;
    asm("{ .reg .u64 t; cvta.to.shared.u64 t, %1; cvt.u32.u64 %0, t; }" : "=r"(a) : "l"(p));
    return a;
}
__device__ __forceinline__ void cp16(uint32_t saddr, const void* gaddr) {
    asm volatile("cp.async.ca.shared.global [%0], [%1], 16;" :: "r"(saddr), "l"(gaddr));
}
__device__ __forceinline__ void cp_commit() {
    asm volatile("cp.async.commit_group;" ::: "memory");
}
template <int N>
__device__ __forceinline__ void cp_wait() {
    asm volatile("cp.async.wait_group %0;" :: "n"(N) : "memory");
}
__device__ __forceinline__ void ldmx4(uint32_t* r, uint32_t addr) {
    asm volatile("ldmatrix.sync.aligned.m8n8.x4.shared.b16 {%0,%1,%2,%3}, [%4];"
                 : "=r"(r[0]), "=r"(r[1]), "=r"(r[2]), "=r"(r[3]) : "r"(addr));
}
__device__ __forceinline__ void ldmx4t(uint32_t* r, uint32_t addr) {
    asm volatile("ldmatrix.sync.aligned.m8n8.x4.trans.shared.b16 {%0,%1,%2,%3}, [%4];"
                 : "=r"(r[0]), "=r"(r[1]), "=r"(r[2]), "=r"(r[3]) : "r"(addr));
}
__device__ __forceinline__ void mma_f16(float* c, const uint32_t* a, uint32_t b0, uint32_t b1) {
    asm volatile(
        "mma.sync.aligned.m16n8k16.row.col.f32.f16.f16.f32 "
        "{%0,%1,%2,%3}, {%4,%5,%6,%7}, {%8,%9}, {%0,%1,%2,%3};"
        : "+f"(c[0]), "+f"(c[1]), "+f"(c[2]), "+f"(c[3])
        : "r"(a[0]), "r"(a[1]), "r"(a[2]), "r"(a[3]), "r"(b0), "r"(b1));
}
__device__ __forceinline__ float ex2f(float x) {
    float y;
    asm("ex2.approx.f32 %0, %1;" : "=f"(y) : "f"(x));
    return y;
}
__device__ __forceinline__ __half2 h2ex2(__half2 x) {
    __half2 y;
    asm("ex2.approx.f16x2 %0, %1;" : "=r"(*(uint32_t*)&y) : "r"(*(uint32_t*)&x));
    return y;
}

// ---------------------------------------------------------------------------
// Merged prep: blocks [0,4096) round x to fp16; blocks [4096,7168) transpose W.
// ---------------------------------------------------------------------------
__global__ __launch_bounds__(256) void prep_kernel(const float4* __restrict__ x,
                                                   const float* __restrict__ W)
{
    if (blockIdx.x < 4096) {
        int i = blockIdx.x * 256 + threadIdx.x;
        float4 v = x[i];
        ((__half2*)g_xh)[2 * i + 0] = __floats2half2_rn(v.x, v.y);
        ((__half2*)g_xh)[2 * i + 1] = __floats2half2_rn(v.z, v.w);
    } else {
        __shared__ float t[32][33];
        int b = blockIdx.x - 4096;              // 3072 blocks
        int d0 = (b & 31) * 32;                 // 32 d-tiles
        int f0 = ((b >> 5) % 6) * 32;           // 6 f-tiles
        int h = b / 192;                        // 16 heads
        int xx = threadIdx.x & 31, yy = threadIdx.x >> 5;   // 32 x 8
        const float* Wh = W + (size_t)h * EMB * FDIM;
        #pragma unroll
        for (int j = 0; j < 32; j += 8)
            t[yy + j][xx] = Wh[(size_t)(d0 + yy + j) * FDIM + f0 + xx];
        __syncthreads();
        #pragma unroll
        for (int j = 0; j < 32; j += 8)
            g_wth[(size_t)(h * FDIM + f0 + yy + j) * EMB + d0 + xx] = __float2half(t[xx][yy + j]);
    }
}

// ---------------------------------------------------------------------------
// QKV GEMM fp16: C[4096, 3072] = xh @ Wt^T via mma.m16n8k16 + ldmatrix.
// CTA 128x128x64(h), 2-stage cp.async (72KB), 4 warps, 3 CTAs/SM.
// Single-barrier double-buffer mainloop (prefetch issued after top sync).
// ---------------------------------------------------------------------------
static constexpr int CTA_M = 128;
static constexpr int CTA_N = 128;
static constexpr int CTA_K = 64;           // halves per stage
static constexpr int GST = 2;
static constexpr int LDAh = 72;            // halves; 144 B rows (9x16 -> CF ldmatrix)
static constexpr int A_H = CTA_M * LDAh;   // 9216
static constexpr int B_H = CTA_N * LDAh;   // 9216
static constexpr int STG_H = A_H + B_H;    // 18432
static constexpr int QKV_SMEM = GST * STG_H * 2;  // 73728 B
static constexpr int KIT = EMB / CTA_K;    // 16

__global__ __launch_bounds__(128, 3) void qkv_mma_kernel(const float* __restrict__ bias)
{
    extern __shared__ __half smh[];
    const int tid = threadIdx.x;
    const int wid = tid >> 5, lane = tid & 31;
    const int t4 = lane & 3, g = lane >> 2;
    const int rowBase = blockIdx.x * CTA_M;
    const int colBase = blockIdx.y * CTA_N;
    const int warp_m0 = (wid >> 1) * 64;
    const int warp_n0 = (wid & 1) * 64;

    const uint32_t sb = smem_u32(smh);
    const __half* gA = g_xh + (size_t)rowBase * EMB;
    const __half* gB = g_wth + (size_t)colBase * EMB;

    auto load_stage = [&](int s, int k0) {
        uint32_t As = sb + (s * STG_H) * 2;
        uint32_t Bs = As + A_H * 2;
        #pragma unroll
        for (int q = 0; q < 8; q++) {
            int c = tid + q * 128;
            int row = c >> 3, ch = (c & 7) * 8;
            cp16(As + (row * LDAh + ch) * 2, gA + (size_t)row * EMB + k0 + ch);
        }
        #pragma unroll
        for (int q = 0; q < 8; q++) {
            int c = tid + q * 128;
            int row = c >> 3, ch = (c & 7) * 8;
            cp16(Bs + (row * LDAh + ch) * 2, gB + (size_t)row * EMB + k0 + ch);
        }
    };

    float acc[4][8][4];
    #pragma unroll
    for (int i = 0; i < 4; i++)
        #pragma unroll
        for (int j = 0; j < 8; j++)
            #pragma unroll
            for (int r = 0; r < 4; r++) acc[i][j][r] = 0.f;

    // Prologue: stage 0 only; loop prefetches stage it+1 after each top sync.
    load_stage(0, 0);
    cp_commit();
    cp_wait<0>();
    __syncthreads();

    const int lrow16 = lane & 15;
    const int lcol8 = (lane >> 4) * 8;

    for (int it = 0; it < KIT; it++) {
        if (it > 0) {
            cp_wait<0>();        // stage it's load complete
            __syncthreads();     // all warps done computing stage it-1
        }
        if (it + 1 < KIT) {
            load_stage((it + 1) & 1, (it + 1) * CTA_K);
            cp_commit();
        }

        uint32_t As = sb + ((it & 1) * STG_H) * 2;
        uint32_t Bs = As + A_H * 2;

        #pragma unroll
        for (int kc = 0; kc < 4; kc++) {
            uint32_t a[4][4];
            #pragma unroll
            for (int mi = 0; mi < 4; mi++)
                ldmx4(a[mi], As + ((warp_m0 + mi * 16 + lrow16) * LDAh + kc * 16 + lcol8) * 2);
            #pragma unroll
            for (int np = 0; np < 4; np++) {
                uint32_t bf[4];
                ldmx4(bf, Bs + ((warp_n0 + np * 16 + lrow16) * LDAh + kc * 16 + lcol8) * 2);
                #pragma unroll
                for (int mi = 0; mi < 4; mi++) {
                    mma_f16(acc[mi][2 * np + 0], a[mi], bf[0], bf[2]);
                    mma_f16(acc[mi][2 * np + 1], a[mi], bf[1], bf[3]);
                }
            }
        }
    }

    const float QSC = 0.1803368801f;   // 0.125 * log2(e)
    #pragma unroll
    for (int mi = 0; mi < 4; mi++) {
        #pragma unroll
        for (int nj = 0; nj < 8; nj++) {
            int row0 = rowBase + warp_m0 + mi * 16 + g;
            int n = colBase + warp_n0 + nj * 8 + 2 * t4;
            int h = n / FDIM, f = n - h * FDIM;
            __half* dstbuf = (f < 64) ? g_k : ((f < 128) ? g_q : g_v);
            float sc = (f >= 64 && f < 128) ? QSC : 1.0f;
            int fd = f & 63;
            float2 bv = make_float2(bias[h * FDIM + f], bias[h * FDIM + f + 1]);
            #pragma unroll
            for (int half_ = 0; half_ < 2; half_++) {
                int r = row0 + half_ * 8;
                int b = r >> 11, ns = r & (SEQ - 1);
                __half2 ov = __floats2half2_rn((acc[mi][nj][half_ * 2 + 0] + bv.x) * sc,
                                               (acc[mi][nj][half_ * 2 + 1] + bv.y) * sc);
                *(__half2*)(dstbuf + (((size_t)(b * NHEAD + h)) * SEQ + ns) * HD + fd) = ov;
            }
        }
    }
}

// ---------------------------------------------------------------------------
// Causal flash attention fp16 (FA2). LPT-balanced schedule (R14):
// 512 items (qt, bh); item j: qt = 15 - j/32, bh = j&31; grid 296 = 2/SM;
// CTA i runs item i, then item 591-i (valid i >= 80).
// Single-barrier double-buffer KV mainloop (prefetch after top sync).
// ---------------------------------------------------------------------------
static constexpr int LDH = 72;                       // halves; 144 B rows
static constexpr int OFFQ = 0;
static constexpr int KVT_H = 64 * LDH;               // 4608 halves per K or V tile
static constexpr int OFFKV = 128 * LDH;
static constexpr int ATT_SMEM = (OFFKV + 4 * KVT_H) * 2;  // 55296 B
static constexpr int ATT_GRID = 296;                 // 2 x 148 SMs
static constexpr int NITEMS = 512;                   // 16 qt x 32 bh
static constexpr int PAIR_SUM = NITEMS - 1 + (ATT_GRID - (NITEMS - ATT_GRID));  // 591

__global__ __launch_bounds__(256, 2) void attn_fa_kernel(float* __restrict__ out)
{
    extern __shared__ __half sh[];
    const int tid = threadIdx.x, wid = tid >> 5, lane = tid & 31;
    const int t4 = lane & 3, g = lane >> 2;
    const int cta = blockIdx.x;                      // 0..295

    const uint32_t sb = smem_u32(sh);
    const int lrow16 = lane & 15;
    const int lcol8 = (lane >> 4) * 8;
    const int v_row = ((lane >> 4) << 3) + (lane & 7);
    const int v_col = ((lane >> 3) & 1) * 8;

    #pragma unroll 1
    for (int pass = 0; pass < 2; pass++) {
        const int j = pass ? (PAIR_SUM - cta) : cta;   // 591 - cta on pass 1
        if (j >= NITEMS) continue;     // pass 1 invalid for cta < 80

        const int qt = 15 - (j >> 5);
        const int bh = j & 31;
        const int qbase = qt * 128;

        const __half* Qg = g_q + (size_t)bh * SEQ * HD + (size_t)qbase * HD;
        const __half* Kg = g_k + (size_t)bh * SEQ * HD;
        const __half* Vg = g_v + (size_t)bh * SEQ * HD;

        auto load_kv = [&](int st, int jt) {
            uint32_t kb = sb + (OFFKV + st * 2 * KVT_H) * 2;
            const __half* kg = Kg + (size_t)jt * 64 * HD;
            const __half* vg = Vg + (size_t)jt * 64 * HD;
            #pragma unroll
            for (int q = 0; q < 2; q++) {
                int c = tid + q * 256;
                int row = c >> 3, ch = (c & 7) * 8;
                cp16(kb + (row * LDH + ch) * 2, kg + (size_t)row * HD + ch);
                cp16(kb + (KVT_H + row * LDH + ch) * 2, vg + (size_t)row * HD + ch);
            }
        };

        // Prologue: Q + KV tile 0; loop prefetches jt+1 after each top sync.
        #pragma unroll
        for (int q = 0; q < 4; q++) {
            int c = tid + q * 256;
            int row = c >> 3, ch = (c & 7) * 8;
            cp16(sb + (OFFQ + row * LDH + ch) * 2, Qg + (size_t)row * HD + ch);
        }
        load_kv(0, 0);
        cp_commit();
        cp_wait<0>();
        __syncthreads();

        uint32_t qf[4][4];
        #pragma unroll
        for (int kc = 0; kc < 4; kc++)
            ldmx4(qf[kc], sb + (OFFQ + (wid * 16 + lrow16) * LDH + kc * 16 + lcol8) * 2);

        float oacc[8][4];
        #pragma unroll
        for (int jj = 0; jj < 8; jj++)
            #pragma unroll
            for (int r = 0; r < 4; r++) oacc[jj][r] = 0.f;
        float mrow[2] = {-1e30f, -1e30f};
        float lrow[2] = {0.f, 0.f};

        const int wrmin = qbase + wid * 16;
        const int wrmax = wrmin + 15;
        const int ntiles = 2 * qt + 2;

        for (int jt = 0; jt < ntiles; jt++) {
            if (jt > 0) {
                cp_wait<0>();        // tile jt's load complete
                __syncthreads();     // all warps done with tile jt-1's buffer
            }
            if (jt + 1 < ntiles) {
                load_kv((jt + 1) & 1, jt + 1);
                cp_commit();
            }

            const int kb0 = jt * 64;
            uint32_t Ks = sb + (OFFKV + (jt & 1) * 2 * KVT_H) * 2;
            uint32_t Vs = Ks + KVT_H * 2;

            if (kb0 <= wrmax) {
                // ---- S = Q @ K^T (64 keys) ----
                float sacc[8][4];
                #pragma unroll
                for (int jj = 0; jj < 8; jj++)
                    #pragma unroll
                    for (int r = 0; r < 4; r++) sacc[jj][r] = 0.f;

                #pragma unroll
                for (int kc = 0; kc < 4; kc++) {
                    #pragma unroll
                    for (int np = 0; np < 4; np++) {
                        uint32_t bf[4];
                        ldmx4(bf, Ks + ((np * 16 + lrow16) * LDH + kc * 16 + lcol8) * 2);
                        mma_f16(sacc[2 * np + 0], qf[kc], bf[0], bf[2]);
                        mma_f16(sacc[2 * np + 1], qf[kc], bf[1], bf[3]);
                    }
                }

                // ---- causal mask (diagonal region only) ----
                if (kb0 + 63 > wrmin) {
                    #pragma unroll
                    for (int nf = 0; nf < 8; nf++) {
                        int key = kb0 + nf * 8 + 2 * t4;
                        #pragma unroll
                        for (int r = 0; r < 2; r++) {
                            int qrow = wrmin + r * 8 + g;
                            if (key > qrow)     sacc[nf][r * 2 + 0] = -1e30f;
                            if (key + 1 > qrow) sacc[nf][r * 2 + 1] = -1e30f;
                        }
                    }
                }

                // ---- rowmax (fp32) + alpha ----
                float alpha[2], mn2[2];
                #pragma unroll
                for (int r = 0; r < 2; r++) {
                    float mx = fmaxf(sacc[0][r * 2], sacc[0][r * 2 + 1]);
                    #pragma unroll
                    for (int nf = 1; nf < 8; nf++)
                        mx = fmaxf(mx, fmaxf(sacc[nf][r * 2], sacc[nf][r * 2 + 1]));
                    mx = fmaxf(mx, __shfl_xor_sync(0xffffffffu, mx, 1));
                    mx = fmaxf(mx, __shfl_xor_sync(0xffffffffu, mx, 2));
                    float mn = fmaxf(mrow[r], mx);
                    alpha[r] = ex2f(mrow[r] - mn);
                    mrow[r] = mn;
                    mn2[r] = mn;
                }

                // ---- exp in f16x2 (P born packed) ----
                __half2 ph2[8][2];
                #pragma unroll
                for (int nf = 0; nf < 8; nf++)
                    #pragma unroll
                    for (int r = 0; r < 2; r++)
                        ph2[nf][r] = h2ex2(__floats2half2_rn(sacc[nf][r * 2 + 0] - mn2[r],
                                                             sacc[nf][r * 2 + 1] - mn2[r]));

                // ---- row sum: hadd2 pairs then f32 ----
                #pragma unroll
                for (int r = 0; r < 2; r++) {
                    __half2 q01 = __hadd2(ph2[0][r], ph2[1][r]);
                    __half2 q23 = __hadd2(ph2[2][r], ph2[3][r]);
                    __half2 q45 = __hadd2(ph2[4][r], ph2[5][r]);
                    __half2 q67 = __hadd2(ph2[6][r], ph2[7][r]);
                    float2 f0 = __half22float2(q01);
                    float2 f1 = __half22float2(q23);
                    float2 f2 = __half22float2(q45);
                    float2 f3 = __half22float2(q67);
                    float rs = ((f0.x + f0.y) + (f1.x + f1.y)) + ((f2.x + f2.y) + (f3.x + f3.y));
                    rs += __shfl_xor_sync(0xffffffffu, rs, 1);
                    rs += __shfl_xor_sync(0xffffffffu, rs, 2);
                    lrow[r] = lrow[r] * alpha[r] + rs;
                }

                // ---- O rescale ----
                #pragma unroll
                for (int nf = 0; nf < 8; nf++) {
                    oacc[nf][0] *= alpha[0]; oacc[nf][1] *= alpha[0];
                    oacc[nf][2] *= alpha[1]; oacc[nf][3] *= alpha[1];
                }

                // ---- O += P @ V ----
                #pragma unroll
                for (int kc2 = 0; kc2 < 4; kc2++) {
                    uint32_t a[4] = {*(uint32_t*)&ph2[2 * kc2][0],     *(uint32_t*)&ph2[2 * kc2][1],
                                     *(uint32_t*)&ph2[2 * kc2 + 1][0], *(uint32_t*)&ph2[2 * kc2 + 1][1]};
                    #pragma unroll
                    for (int np = 0; np < 4; np++) {
                        uint32_t bf[4];
                        ldmx4t(bf, Vs + ((kc2 * 16 + v_row) * LDH + np * 16 + v_col) * 2);
                        mma_f16(oacc[2 * np + 0], a, bf[0], bf[2]);
                        mma_f16(oacc[2 * np + 1], a, bf[1], bf[3]);
                    }
                }
            }
        }

        // ---- epilogue for this item ----
        const int b = bh >> 4, h = bh & (NHEAD - 1);
        #pragma unroll
        for (int r = 0; r < 2; r++) {
            int qrow = qbase + wid * 16 + r * 8 + g;
            float inv = 1.0f / lrow[r];
            float* op = out + ((size_t)(b * SEQ + qrow)) * EMB + h * HD;
            #pragma unroll
            for (int nf = 0; nf < 8; nf++) {
                float2 ov = make_float2(oacc[nf][r * 2] * inv, oacc[nf][r * 2 + 1] * inv);
                *(float2*)(op + nf * 8 + 2 * t4) = ov;
            }
        }
        __syncthreads();   // all warps done with smem before next item reuses it
    }
}

// ---------------------------------------------------------------------------
// Host launcher
// ---------------------------------------------------------------------------
extern "C" void kernel_launch(void* const* d_in, const int* in_sizes, int n_in,
                              void* d_out, int out_size)
{
    const float* x    = (const float*)d_in[0];  // [2,2048,1024]
    const float* W    = (const float*)d_in[1];  // [16,1024,192]
    const float* bias = (const float*)d_in[2];  // [16,192]
    float* out = (float*)d_out;                 // [2,2048,1024]

    prep_kernel<<<4096 + 3072, 256>>>((const float4*)x, W);

    static bool smem_set = false;
    if (!smem_set) {
        cudaFuncSetAttribute(qkv_mma_kernel, cudaFuncAttributeMaxDynamicSharedMemorySize, QKV_SMEM);
        cudaFuncSetAttribute(attn_fa_kernel, cudaFuncAttributeMaxDynamicSharedMemorySize, ATT_SMEM);
        smem_set = true;
    }
    qkv_mma_kernel<<<dim3(ROWS / CTA_M, NTOT / CTA_N), 128, QKV_SMEM>>>(bias);

    attn_fa_kernel<<<ATT_GRID, 256, ATT_SMEM>>>(out);
}

// round 16
// speedup vs baseline: 1.2762x; 1.0205x over previous
#include <cuda_runtime.h>
#include <cuda_fp16.h>
#include <cstdint>

#define BATCH 2
#define SEQ 2048
#define NHEAD 16
#define HD 64
#define EMB 1024
#define ROWS (BATCH * SEQ)          // 4096
#define FDIM 192
#define NTOT (NHEAD * FDIM)         // 3072
#define QKV_ELEMS (BATCH * NHEAD * SEQ * HD)

// Scratch (no cudaMalloc allowed) — all fp16
__device__ __align__(1024) __half g_q[QKV_ELEMS];   // pre-scaled by 0.125*log2(e)
__device__ __align__(1024) __half g_k[QKV_ELEMS];
__device__ __align__(1024) __half g_v[QKV_ELEMS];
__device__ __align__(1024) __half g_xh[ROWS * EMB];
__device__ __align__(1024) __half g_wth[NTOT * EMB];   // W^T [h*192+f][1024]

// ---------------------------------------------------------------------------
// PTX helpers
// ---------------------------------------------------------------------------
__device__ __forceinline__ uint32_t smem_u32(const void* p) {
    uint32_t a;
    asm("{ .reg .u64 t; cvta.to.shared.u64 t, %1; cvt.u32.u64 %0, t; }" : "=r"(a) : "l"(p));
    return a;
}
__device__ __forceinline__ void cp16(uint32_t saddr, const void* gaddr) {
    asm volatile("cp.async.ca.shared.global [%0], [%1], 16;" :: "r"(saddr), "l"(gaddr));
}
__device__ __forceinline__ void cp_commit() {
    asm volatile("cp.async.commit_group;" ::: "memory");
}
template <int N>
__device__ __forceinline__ void cp_wait() {
    asm volatile("cp.async.wait_group %0;" :: "n"(N) : "memory");
}
__device__ __forceinline__ void ldmx4(uint32_t* r, uint32_t addr) {
    asm volatile("ldmatrix.sync.aligned.m8n8.x4.shared.b16 {%0,%1,%2,%3}, [%4];"
                 : "=r"(r[0]), "=r"(r[1]), "=r"(r[2]), "=r"(r[3]) : "r"(addr));
}
__device__ __forceinline__ void ldmx4t(uint32_t* r, uint32_t addr) {
    asm volatile("ldmatrix.sync.aligned.m8n8.x4.trans.shared.b16 {%0,%1,%2,%3}, [%4];"
                 : "=r"(r[0]), "=r"(r[1]), "=r"(r[2]), "=r"(r[3]) : "r"(addr));
}
__device__ __forceinline__ void mma_f16(float* c, const uint32_t* a, uint32_t b0, uint32_t b1) {
    asm volatile(
        "mma.sync.aligned.m16n8k16.row.col.f32.f16.f16.f32 "
        "{%0,%1,%2,%3}, {%4,%5,%6,%7}, {%8,%9}, {%0,%1,%2,%3};"
        : "+f"(c[0]), "+f"(c[1]), "+f"(c[2]), "+f"(c[3])
        : "r"(a[0]), "r"(a[1]), "r"(a[2]), "r"(a[3]), "r"(b0), "r"(b1));
}
// fp16-accumulate HMMA: D(half2 x2) = A*B + C
__device__ __forceinline__ void mma_f16acc(uint32_t* d, const uint32_t* a,
                                           uint32_t b0, uint32_t b1,
                                           uint32_t c0, uint32_t c1) {
    asm volatile(
        "mma.sync.aligned.m16n8k16.row.col.f16.f16.f16.f16 "
        "{%0,%1}, {%2,%3,%4,%5}, {%6,%7}, {%8,%9};"
        : "=r"(d[0]), "=r"(d[1])
        : "r"(a[0]), "r"(a[1]), "r"(a[2]), "r"(a[3]), "r"(b0), "r"(b1),
          "r"(c0), "r"(c1));
}
__device__ __forceinline__ float ex2f(float x) {
    float y;
    asm("ex2.approx.f32 %0, %1;" : "=f"(y) : "f"(x));
    return y;
}
__device__ __forceinline__ __half2 h2ex2(__half2 x) {
    __half2 y;
    asm("ex2.approx.f16x2 %0, %1;" : "=r"(*(uint32_t*)&y) : "r"(*(uint32_t*)&x));
    return y;
}

// ---------------------------------------------------------------------------
// Merged prep: blocks [0,4096) round x to fp16; blocks [4096,7168) transpose W.
// ---------------------------------------------------------------------------
__global__ __launch_bounds__(256) void prep_kernel(const float4* __restrict__ x,
                                                   const float* __restrict__ W)
{
    if (blockIdx.x < 4096) {
        int i = blockIdx.x * 256 + threadIdx.x;
        float4 v = x[i];
        ((__half2*)g_xh)[2 * i + 0] = __floats2half2_rn(v.x, v.y);
        ((__half2*)g_xh)[2 * i + 1] = __floats2half2_rn(v.z, v.w);
    } else {
        __shared__ float t[32][33];
        int b = blockIdx.x - 4096;              // 3072 blocks
        int d0 = (b & 31) * 32;                 // 32 d-tiles
        int f0 = ((b >> 5) % 6) * 32;           // 6 f-tiles
        int h = b / 192;                        // 16 heads
        int xx = threadIdx.x & 31, yy = threadIdx.x >> 5;   // 32 x 8
        const float* Wh = W + (size_t)h * EMB * FDIM;
        #pragma unroll
        for (int j = 0; j < 32; j += 8)
            t[yy + j][xx] = Wh[(size_t)(d0 + yy + j) * FDIM + f0 + xx];
        __syncthreads();
        #pragma unroll
        for (int j = 0; j < 32; j += 8)
            g_wth[(size_t)(h * FDIM + f0 + yy + j) * EMB + d0 + xx] = __float2half(t[xx][yy + j]);
    }
}

// ---------------------------------------------------------------------------
// QKV GEMM fp16: C[4096, 3072] = xh @ Wt^T via mma.m16n8k16 + ldmatrix.
// CTA 128x128x64(h), 2-stage cp.async (72KB), 4 warps.
// fp16-ACCUMULATE MMAs chained across each K=64 stage (zero-C first step),
// promoted into fp32 master accumulators once per stage (overlaps next MMAs).
// ---------------------------------------------------------------------------
static constexpr int CTA_M = 128;
static constexpr int CTA_N = 128;
static constexpr int CTA_K = 64;           // halves per stage
static constexpr int GST = 2;
static constexpr int LDAh = 72;            // halves; 144 B rows (9x16 -> CF ldmatrix)
static constexpr int A_H = CTA_M * LDAh;   // 9216
static constexpr int B_H = CTA_N * LDAh;   // 9216
static constexpr int STG_H = A_H + B_H;    // 18432
static constexpr int QKV_SMEM = GST * STG_H * 2;  // 73728 B
static constexpr int KIT = EMB / CTA_K;    // 16

__global__ __launch_bounds__(128, 2) void qkv_mma_kernel(const float* __restrict__ bias)
{
    extern __shared__ __half smh[];
    const int tid = threadIdx.x;
    const int wid = tid >> 5, lane = tid & 31;
    const int t4 = lane & 3, g = lane >> 2;
    const int rowBase = blockIdx.x * CTA_M;
    const int colBase = blockIdx.y * CTA_N;
    const int warp_m0 = (wid >> 1) * 64;
    const int warp_n0 = (wid & 1) * 64;

    const uint32_t sb = smem_u32(smh);
    const __half* gA = g_xh + (size_t)rowBase * EMB;
    const __half* gB = g_wth + (size_t)colBase * EMB;

    auto load_stage = [&](int s, int k0) {
        uint32_t As = sb + (s * STG_H) * 2;
        uint32_t Bs = As + A_H * 2;
        #pragma unroll
        for (int q = 0; q < 8; q++) {
            int c = tid + q * 128;
            int row = c >> 3, ch = (c & 7) * 8;
            cp16(As + (row * LDAh + ch) * 2, gA + (size_t)row * EMB + k0 + ch);
        }
        #pragma unroll
        for (int q = 0; q < 8; q++) {
            int c = tid + q * 128;
            int row = c >> 3, ch = (c & 7) * 8;
            cp16(Bs + (row * LDAh + ch) * 2, gB + (size_t)row * EMB + k0 + ch);
        }
    };

    float acc[4][8][4];
    #pragma unroll
    for (int i = 0; i < 4; i++)
        #pragma unroll
        for (int j = 0; j < 8; j++)
            #pragma unroll
            for (int r = 0; r < 4; r++) acc[i][j][r] = 0.f;

    // Prologue: stage 0 only; loop prefetches stage it+1 after each top sync.
    load_stage(0, 0);
    cp_commit();
    cp_wait<0>();
    __syncthreads();

    const int lrow16 = lane & 15;
    const int lcol8 = (lane >> 4) * 8;
    const uint32_t zz = 0u;   // zero-C operand for first MMA of each stage

    for (int it = 0; it < KIT; it++) {
        if (it > 0) {
            cp_wait<0>();        // stage it's load complete
            __syncthreads();     // all warps done computing stage it-1
        }
        if (it + 1 < KIT) {
            load_stage((it + 1) & 1, (it + 1) * CTA_K);
            cp_commit();
        }

        uint32_t As = sb + ((it & 1) * STG_H) * 2;
        uint32_t Bs = As + A_H * 2;

        // fp16-accumulated chain over this stage's 4 k16 chunks
        uint32_t acc16[4][8][2];
        #pragma unroll
        for (int kc = 0; kc < 4; kc++) {
            uint32_t a[4][4];
            #pragma unroll
            for (int mi = 0; mi < 4; mi++)
                ldmx4(a[mi], As + ((warp_m0 + mi * 16 + lrow16) * LDAh + kc * 16 + lcol8) * 2);
            #pragma unroll
            for (int np = 0; np < 4; np++) {
                uint32_t bf[4];
                ldmx4(bf, Bs + ((warp_n0 + np * 16 + lrow16) * LDAh + kc * 16 + lcol8) * 2);
                #pragma unroll
                for (int mi = 0; mi < 4; mi++) {
                    if (kc == 0) {
                        mma_f16acc(acc16[mi][2 * np + 0], a[mi], bf[0], bf[2], zz, zz);
                        mma_f16acc(acc16[mi][2 * np + 1], a[mi], bf[1], bf[3], zz, zz);
                    } else {
                        mma_f16acc(acc16[mi][2 * np + 0], a[mi], bf[0], bf[2],
                                   acc16[mi][2 * np + 0][0], acc16[mi][2 * np + 0][1]);
                        mma_f16acc(acc16[mi][2 * np + 1], a[mi], bf[1], bf[3],
                                   acc16[mi][2 * np + 1][0], acc16[mi][2 * np + 1][1]);
                    }
                }
            }
        }

        // Promote this stage's fp16 partials into fp32 master accumulators
        #pragma unroll
        for (int mi = 0; mi < 4; mi++) {
            #pragma unroll
            for (int nj = 0; nj < 8; nj++) {
                float2 f0 = __half22float2(*(__half2*)&acc16[mi][nj][0]);
                float2 f1 = __half22float2(*(__half2*)&acc16[mi][nj][1]);
                acc[mi][nj][0] += f0.x;
                acc[mi][nj][1] += f0.y;
                acc[mi][nj][2] += f1.x;
                acc[mi][nj][3] += f1.y;
            }
        }
    }

    const float QSC = 0.1803368801f;   // 0.125 * log2(e)
    #pragma unroll
    for (int mi = 0; mi < 4; mi++) {
        #pragma unroll
        for (int nj = 0; nj < 8; nj++) {
            int row0 = rowBase + warp_m0 + mi * 16 + g;
            int n = colBase + warp_n0 + nj * 8 + 2 * t4;
            int h = n / FDIM, f = n - h * FDIM;
            __half* dstbuf = (f < 64) ? g_k : ((f < 128) ? g_q : g_v);
            float sc = (f >= 64 && f < 128) ? QSC : 1.0f;
            int fd = f & 63;
            float2 bv = make_float2(bias[h * FDIM + f], bias[h * FDIM + f + 1]);
            #pragma unroll
            for (int half_ = 0; half_ < 2; half_++) {
                int r = row0 + half_ * 8;
                int b = r >> 11, ns = r & (SEQ - 1);
                __half2 ov = __floats2half2_rn((acc[mi][nj][half_ * 2 + 0] + bv.x) * sc,
                                               (acc[mi][nj][half_ * 2 + 1] + bv.y) * sc);
                *(__half2*)(dstbuf + (((size_t)(b * NHEAD + h)) * SEQ + ns) * HD + fd) = ov;
            }
        }
    }
}

// ---------------------------------------------------------------------------
// Causal flash attention fp16 (FA2) — byte-identical to R15 (best measured).
// LPT-balanced schedule: 512 items (qt, bh); item j: qt = 15 - j/32, bh = j&31;
// grid 296 = 2/SM; CTA i runs item i, then item 591-i (valid i >= 80).
// Single-barrier double-buffer KV mainloop.
// ---------------------------------------------------------------------------
static constexpr int LDH = 72;                       // halves; 144 B rows
static constexpr int OFFQ = 0;
static constexpr int KVT_H = 64 * LDH;               // 4608 halves per K or V tile
static constexpr int OFFKV = 128 * LDH;
static constexpr int ATT_SMEM = (OFFKV + 4 * KVT_H) * 2;  // 55296 B
static constexpr int ATT_GRID = 296;                 // 2 x 148 SMs
static constexpr int NITEMS = 512;                   // 16 qt x 32 bh
static constexpr int PAIR_SUM = NITEMS - 1 + (ATT_GRID - (NITEMS - ATT_GRID));  // 591

__global__ __launch_bounds__(256, 2) void attn_fa_kernel(float* __restrict__ out)
{
    extern __shared__ __half sh[];
    const int tid = threadIdx.x, wid = tid >> 5, lane = tid & 31;
    const int t4 = lane & 3, g = lane >> 2;
    const int cta = blockIdx.x;                      // 0..295

    const uint32_t sb = smem_u32(sh);
    const int lrow16 = lane & 15;
    const int lcol8 = (lane >> 4) * 8;
    const int v_row = ((lane >> 4) << 3) + (lane & 7);
    const int v_col = ((lane >> 3) & 1) * 8;

    #pragma unroll 1
    for (int pass = 0; pass < 2; pass++) {
        const int j = pass ? (PAIR_SUM - cta) : cta;   // 591 - cta on pass 1
        if (j >= NITEMS) continue;     // pass 1 invalid for cta < 80

        const int qt = 15 - (j >> 5);
        const int bh = j & 31;
        const int qbase = qt * 128;

        const __half* Qg = g_q + (size_t)bh * SEQ * HD + (size_t)qbase * HD;
        const __half* Kg = g_k + (size_t)bh * SEQ * HD;
        const __half* Vg = g_v + (size_t)bh * SEQ * HD;

        auto load_kv = [&](int st, int jt) {
            uint32_t kb = sb + (OFFKV + st * 2 * KVT_H) * 2;
            const __half* kg = Kg + (size_t)jt * 64 * HD;
            const __half* vg = Vg + (size_t)jt * 64 * HD;
            #pragma unroll
            for (int q = 0; q < 2; q++) {
                int c = tid + q * 256;
                int row = c >> 3, ch = (c & 7) * 8;
                cp16(kb + (row * LDH + ch) * 2, kg + (size_t)row * HD + ch);
                cp16(kb + (KVT_H + row * LDH + ch) * 2, vg + (size_t)row * HD + ch);
            }
        };

        // Prologue: Q + KV tile 0; loop prefetches jt+1 after each top sync.
        #pragma unroll
        for (int q = 0; q < 4; q++) {
            int c = tid + q * 256;
            int row = c >> 3, ch = (c & 7) * 8;
            cp16(sb + (OFFQ + row * LDH + ch) * 2, Qg + (size_t)row * HD + ch);
        }
        load_kv(0, 0);
        cp_commit();
        cp_wait<0>();
        __syncthreads();

        uint32_t qf[4][4];
        #pragma unroll
        for (int kc = 0; kc < 4; kc++)
            ldmx4(qf[kc], sb + (OFFQ + (wid * 16 + lrow16) * LDH + kc * 16 + lcol8) * 2);

        float oacc[8][4];
        #pragma unroll
        for (int jj = 0; jj < 8; jj++)
            #pragma unroll
            for (int r = 0; r < 4; r++) oacc[jj][r] = 0.f;
        float mrow[2] = {-1e30f, -1e30f};
        float lrow[2] = {0.f, 0.f};

        const int wrmin = qbase + wid * 16;
        const int wrmax = wrmin + 15;
        const int ntiles = 2 * qt + 2;

        for (int jt = 0; jt < ntiles; jt++) {
            if (jt > 0) {
                cp_wait<0>();        // tile jt's load complete
                __syncthreads();     // all warps done with tile jt-1's buffer
            }
            if (jt + 1 < ntiles) {
                load_kv((jt + 1) & 1, jt + 1);
                cp_commit();
            }

            const int kb0 = jt * 64;
            uint32_t Ks = sb + (OFFKV + (jt & 1) * 2 * KVT_H) * 2;
            uint32_t Vs = Ks + KVT_H * 2;

            if (kb0 <= wrmax) {
                // ---- S = Q @ K^T (64 keys) ----
                float sacc[8][4];
                #pragma unroll
                for (int jj = 0; jj < 8; jj++)
                    #pragma unroll
                    for (int r = 0; r < 4; r++) sacc[jj][r] = 0.f;

                #pragma unroll
                for (int kc = 0; kc < 4; kc++) {
                    #pragma unroll
                    for (int np = 0; np < 4; np++) {
                        uint32_t bf[4];
                        ldmx4(bf, Ks + ((np * 16 + lrow16) * LDH + kc * 16 + lcol8) * 2);
                        mma_f16(sacc[2 * np + 0], qf[kc], bf[0], bf[2]);
                        mma_f16(sacc[2 * np + 1], qf[kc], bf[1], bf[3]);
                    }
                }

                // ---- causal mask (diagonal region only) ----
                if (kb0 + 63 > wrmin) {
                    #pragma unroll
                    for (int nf = 0; nf < 8; nf++) {
                        int key = kb0 + nf * 8 + 2 * t4;
                        #pragma unroll
                        for (int r = 0; r < 2; r++) {
                            int qrow = wrmin + r * 8 + g;
                            if (key > qrow)     sacc[nf][r * 2 + 0] = -1e30f;
                            if (key + 1 > qrow) sacc[nf][r * 2 + 1] = -1e30f;
                        }
                    }
                }

                // ---- rowmax (fp32) + alpha ----
                float alpha[2], mn2[2];
                #pragma unroll
                for (int r = 0; r < 2; r++) {
                    float mx = fmaxf(sacc[0][r * 2], sacc[0][r * 2 + 1]);
                    #pragma unroll
                    for (int nf = 1; nf < 8; nf++)
                        mx = fmaxf(mx, fmaxf(sacc[nf][r * 2], sacc[nf][r * 2 + 1]));
                    mx = fmaxf(mx, __shfl_xor_sync(0xffffffffu, mx, 1));
                    mx = fmaxf(mx, __shfl_xor_sync(0xffffffffu, mx, 2));
                    float mn = fmaxf(mrow[r], mx);
                    alpha[r] = ex2f(mrow[r] - mn);
                    mrow[r] = mn;
                    mn2[r] = mn;
                }

                // ---- exp in f16x2 (P born packed) ----
                __half2 ph2[8][2];
                #pragma unroll
                for (int nf = 0; nf < 8; nf++)
                    #pragma unroll
                    for (int r = 0; r < 2; r++)
                        ph2[nf][r] = h2ex2(__floats2half2_rn(sacc[nf][r * 2 + 0] - mn2[r],
                                                             sacc[nf][r * 2 + 1] - mn2[r]));

                // ---- row sum: hadd2 pairs then f32 ----
                #pragma unroll
                for (int r = 0; r < 2; r++) {
                    __half2 q01 = __hadd2(ph2[0][r], ph2[1][r]);
                    __half2 q23 = __hadd2(ph2[2][r], ph2[3][r]);
                    __half2 q45 = __hadd2(ph2[4][r], ph2[5][r]);
                    __half2 q67 = __hadd2(ph2[6][r], ph2[7][r]);
                    float2 f0 = __half22float2(q01);
                    float2 f1 = __half22float2(q23);
                    float2 f2 = __half22float2(q45);
                    float2 f3 = __half22float2(q67);
                    float rs = ((f0.x + f0.y) + (f1.x + f1.y)) + ((f2.x + f2.y) + (f3.x + f3.y));
                    rs += __shfl_xor_sync(0xffffffffu, rs, 1);
                    rs += __shfl_xor_sync(0xffffffffu, rs, 2);
                    lrow[r] = lrow[r] * alpha[r] + rs;
                }

                // ---- O rescale ----
                #pragma unroll
                for (int nf = 0; nf < 8; nf++) {
                    oacc[nf][0] *= alpha[0]; oacc[nf][1] *= alpha[0];
                    oacc[nf][2] *= alpha[1]; oacc[nf][3] *= alpha[1];
                }

                // ---- O += P @ V ----
                #pragma unroll
                for (int kc2 = 0; kc2 < 4; kc2++) {
                    uint32_t a[4] = {*(uint32_t*)&ph2[2 * kc2][0],     *(uint32_t*)&ph2[2 * kc2][1],
                                     *(uint32_t*)&ph2[2 * kc2 + 1][0], *(uint32_t*)&ph2[2 * kc2 + 1][1]};
                    #pragma unroll
                    for (int np = 0; np < 4; np++) {
                        uint32_t bf[4];
                        ldmx4t(bf, Vs + ((kc2 * 16 + v_row) * LDH + np * 16 + v_col) * 2);
                        mma_f16(oacc[2 * np + 0], a, bf[0], bf[2]);
                        mma_f16(oacc[2 * np + 1], a, bf[1], bf[3]);
                    }
                }
            }
        }

        // ---- epilogue for this item ----
        const int b = bh >> 4, h = bh & (NHEAD - 1);
        #pragma unroll
        for (int r = 0; r < 2; r++) {
            int qrow = qbase + wid * 16 + r * 8 + g;
            float inv = 1.0f / lrow[r];
            float* op = out + ((size_t)(b * SEQ + qrow)) * EMB + h * HD;
            #pragma unroll
            for (int nf = 0; nf < 8; nf++) {
                float2 ov = make_float2(oacc[nf][r * 2] * inv, oacc[nf][r * 2 + 1] * inv);
                *(float2*)(op + nf * 8 + 2 * t4) = ov;
            }
        }
        __syncthreads();   // all warps done with smem before next item reuses it
    }
}

// ---------------------------------------------------------------------------
// Host launcher
// ---------------------------------------------------------------------------
extern "C" void kernel_launch(void* const* d_in, const int* in_sizes, int n_in,
                              void* d_out, int out_size)
{
    const float* x    = (const float*)d_in[0];  // [2,2048,1024]
    const float* W    = (const float*)d_in[1];  // [16,1024,192]
    const float* bias = (const float*)d_in[2];  // [16,192]
    float* out = (float*)d_out;                 // [2,2048,1024]

    prep_kernel<<<4096 + 3072, 256>>>((const float4*)x, W);

    static bool smem_set = false;
    if (!smem_set) {
        cudaFuncSetAttribute(qkv_mma_kernel, cudaFuncAttributeMaxDynamicSharedMemorySize, QKV_SMEM);
        cudaFuncSetAttribute(attn_fa_kernel, cudaFuncAttributeMaxDynamicSharedMemorySize, ATT_SMEM);
        smem_set = true;
    }
    qkv_mma_kernel<<<dim3(ROWS / CTA_M, NTOT / CTA_N), 128, QKV_SMEM>>>(bias);

    attn_fa_kernel<<<ATT_GRID, 256, ATT_SMEM>>>(out);
}

// round 17
// speedup vs baseline: 1.2967x; 1.0161x over previous
#include <cuda_runtime.h>
#include <cuda_fp16.h>
#include <cstdint>

#define BATCH 2
#define SEQ 2048
#define NHEAD 16
#define HD 64
#define EMB 1024
#define ROWS (BATCH * SEQ)          // 4096
#define FDIM 192
#define NTOT (NHEAD * FDIM)         // 3072
#define QKV_ELEMS (BATCH * NHEAD * SEQ * HD)

// Scratch (no cudaMalloc allowed) — all fp16
__device__ __align__(1024) __half g_q[QKV_ELEMS];   // pre-scaled by 0.125*log2(e)
__device__ __align__(1024) __half g_k[QKV_ELEMS];
__device__ __align__(1024) __half g_v[QKV_ELEMS];
__device__ __align__(1024) __half g_xh[ROWS * EMB];
__device__ __align__(1024) __half g_wth[NTOT * EMB];   // W^T [h*192+f][1024]

// ---------------------------------------------------------------------------
// PTX helpers
// ---------------------------------------------------------------------------
__device__ __forceinline__ uint32_t smem_u32(const void* p) {
    uint32_t a;
    asm("{ .reg .u64 t; cvta.to.shared.u64 t, %1; cvt.u32.u64 %0, t; }" : "=r"(a) : "l"(p));
    return a;
}
__device__ __forceinline__ void cp16(uint32_t saddr, const void* gaddr) {
    asm volatile("cp.async.ca.shared.global [%0], [%1], 16;" :: "r"(saddr), "l"(gaddr));
}
__device__ __forceinline__ void cp_commit() {
    asm volatile("cp.async.commit_group;" ::: "memory");
}
template <int N>
__device__ __forceinline__ void cp_wait() {
    asm volatile("cp.async.wait_group %0;" :: "n"(N) : "memory");
}
__device__ __forceinline__ void ldmx4(uint32_t* r, uint32_t addr) {
    asm volatile("ldmatrix.sync.aligned.m8n8.x4.shared.b16 {%0,%1,%2,%3}, [%4];"
                 : "=r"(r[0]), "=r"(r[1]), "=r"(r[2]), "=r"(r[3]) : "r"(addr));
}
__device__ __forceinline__ void ldmx4t(uint32_t* r, uint32_t addr) {
    asm volatile("ldmatrix.sync.aligned.m8n8.x4.trans.shared.b16 {%0,%1,%2,%3}, [%4];"
                 : "=r"(r[0]), "=r"(r[1]), "=r"(r[2]), "=r"(r[3]) : "r"(addr));
}
__device__ __forceinline__ void mma_f16(float* c, const uint32_t* a, uint32_t b0, uint32_t b1) {
    asm volatile(
        "mma.sync.aligned.m16n8k16.row.col.f32.f16.f16.f32 "
        "{%0,%1,%2,%3}, {%4,%5,%6,%7}, {%8,%9}, {%0,%1,%2,%3};"
        : "+f"(c[0]), "+f"(c[1]), "+f"(c[2]), "+f"(c[3])
        : "r"(a[0]), "r"(a[1]), "r"(a[2]), "r"(a[3]), "r"(b0), "r"(b1));
}
// fp16-accumulate HMMA: D(half2 x2) = A*B + C
__device__ __forceinline__ void mma_f16acc(uint32_t* d, const uint32_t* a,
                                           uint32_t b0, uint32_t b1,
                                           uint32_t c0, uint32_t c1) {
    asm volatile(
        "mma.sync.aligned.m16n8k16.row.col.f16.f16.f16.f16 "
        "{%0,%1}, {%2,%3,%4,%5}, {%6,%7}, {%8,%9};"
        : "=r"(d[0]), "=r"(d[1])
        : "r"(a[0]), "r"(a[1]), "r"(a[2]), "r"(a[3]), "r"(b0), "r"(b1),
          "r"(c0), "r"(c1));
}
__device__ __forceinline__ float ex2f(float x) {
    float y;
    asm("ex2.approx.f32 %0, %1;" : "=f"(y) : "f"(x));
    return y;
}
__device__ __forceinline__ __half2 h2ex2(__half2 x) {
    __half2 y;
    asm("ex2.approx.f16x2 %0, %1;" : "=r"(*(uint32_t*)&y) : "r"(*(uint32_t*)&x));
    return y;
}

// ---------------------------------------------------------------------------
// Merged prep: blocks [0,4096) round x to fp16; blocks [4096,7168) transpose W.
// ---------------------------------------------------------------------------
__global__ __launch_bounds__(256) void prep_kernel(const float4* __restrict__ x,
                                                   const float* __restrict__ W)
{
    if (blockIdx.x < 4096) {
        int i = blockIdx.x * 256 + threadIdx.x;
        float4 v = x[i];
        ((__half2*)g_xh)[2 * i + 0] = __floats2half2_rn(v.x, v.y);
        ((__half2*)g_xh)[2 * i + 1] = __floats2half2_rn(v.z, v.w);
    } else {
        __shared__ float t[32][33];
        int b = blockIdx.x - 4096;              // 3072 blocks
        int d0 = (b & 31) * 32;                 // 32 d-tiles
        int f0 = ((b >> 5) % 6) * 32;           // 6 f-tiles
        int h = b / 192;                        // 16 heads
        int xx = threadIdx.x & 31, yy = threadIdx.x >> 5;   // 32 x 8
        const float* Wh = W + (size_t)h * EMB * FDIM;
        #pragma unroll
        for (int j = 0; j < 32; j += 8)
            t[yy + j][xx] = Wh[(size_t)(d0 + yy + j) * FDIM + f0 + xx];
        __syncthreads();
        #pragma unroll
        for (int j = 0; j < 32; j += 8)
            g_wth[(size_t)(h * FDIM + f0 + yy + j) * EMB + d0 + xx] = __float2half(t[xx][yy + j]);
    }
}

// ---------------------------------------------------------------------------
// QKV GEMM fp16: C[4096, 3072] = xh @ Wt^T via mma.m16n8k16 + ldmatrix.
// CTA 128x128x64(h), 2-stage cp.async (72KB), 4 warps.
// fp16-ACCUMULATE MMAs chained across PAIRS of K=64 stages (K=128 per chain),
// promoted into fp32 master accumulators once per pair.
// ---------------------------------------------------------------------------
static constexpr int CTA_M = 128;
static constexpr int CTA_N = 128;
static constexpr int CTA_K = 64;           // halves per stage
static constexpr int GST = 2;
static constexpr int LDAh = 72;            // halves; 144 B rows (9x16 -> CF ldmatrix)
static constexpr int A_H = CTA_M * LDAh;   // 9216
static constexpr int B_H = CTA_N * LDAh;   // 9216
static constexpr int STG_H = A_H + B_H;    // 18432
static constexpr int QKV_SMEM = GST * STG_H * 2;  // 73728 B
static constexpr int KIT = EMB / CTA_K;    // 16 (even -> chains pair cleanly)

__global__ __launch_bounds__(128, 2) void qkv_mma_kernel(const float* __restrict__ bias)
{
    extern __shared__ __half smh[];
    const int tid = threadIdx.x;
    const int wid = tid >> 5, lane = tid & 31;
    const int t4 = lane & 3, g = lane >> 2;
    const int rowBase = blockIdx.x * CTA_M;
    const int colBase = blockIdx.y * CTA_N;
    const int warp_m0 = (wid >> 1) * 64;
    const int warp_n0 = (wid & 1) * 64;

    const uint32_t sb = smem_u32(smh);
    const __half* gA = g_xh + (size_t)rowBase * EMB;
    const __half* gB = g_wth + (size_t)colBase * EMB;

    auto load_stage = [&](int s, int k0) {
        uint32_t As = sb + (s * STG_H) * 2;
        uint32_t Bs = As + A_H * 2;
        #pragma unroll
        for (int q = 0; q < 8; q++) {
            int c = tid + q * 128;
            int row = c >> 3, ch = (c & 7) * 8;
            cp16(As + (row * LDAh + ch) * 2, gA + (size_t)row * EMB + k0 + ch);
        }
        #pragma unroll
        for (int q = 0; q < 8; q++) {
            int c = tid + q * 128;
            int row = c >> 3, ch = (c & 7) * 8;
            cp16(Bs + (row * LDAh + ch) * 2, gB + (size_t)row * EMB + k0 + ch);
        }
    };

    float acc[4][8][4];
    #pragma unroll
    for (int i = 0; i < 4; i++)
        #pragma unroll
        for (int j = 0; j < 8; j++)
            #pragma unroll
            for (int r = 0; r < 4; r++) acc[i][j][r] = 0.f;

    // Prologue: stage 0 only; loop prefetches stage it+1 after each top sync.
    load_stage(0, 0);
    cp_commit();
    cp_wait<0>();
    __syncthreads();

    const int lrow16 = lane & 15;
    const int lcol8 = (lane >> 4) * 8;
    const uint32_t zz = 0u;   // zero-C operand for chain start

    uint32_t acc16[4][8][2];  // fp16 chain accumulators (live across stage pairs)

    for (int it = 0; it < KIT; it++) {
        if (it > 0) {
            cp_wait<0>();        // stage it's load complete
            __syncthreads();     // all warps done computing stage it-1
        }
        if (it + 1 < KIT) {
            load_stage((it + 1) & 1, (it + 1) * CTA_K);
            cp_commit();
        }

        uint32_t As = sb + ((it & 1) * STG_H) * 2;
        uint32_t Bs = As + A_H * 2;

        if ((it & 1) == 0) {
            // Even stage: start a fresh fp16 chain (kc==0 uses zero C)
            #pragma unroll
            for (int kc = 0; kc < 4; kc++) {
                uint32_t a[4][4];
                #pragma unroll
                for (int mi = 0; mi < 4; mi++)
                    ldmx4(a[mi], As + ((warp_m0 + mi * 16 + lrow16) * LDAh + kc * 16 + lcol8) * 2);
                #pragma unroll
                for (int np = 0; np < 4; np++) {
                    uint32_t bf[4];
                    ldmx4(bf, Bs + ((warp_n0 + np * 16 + lrow16) * LDAh + kc * 16 + lcol8) * 2);
                    #pragma unroll
                    for (int mi = 0; mi < 4; mi++) {
                        if (kc == 0) {
                            mma_f16acc(acc16[mi][2 * np + 0], a[mi], bf[0], bf[2], zz, zz);
                            mma_f16acc(acc16[mi][2 * np + 1], a[mi], bf[1], bf[3], zz, zz);
                        } else {
                            mma_f16acc(acc16[mi][2 * np + 0], a[mi], bf[0], bf[2],
                                       acc16[mi][2 * np + 0][0], acc16[mi][2 * np + 0][1]);
                            mma_f16acc(acc16[mi][2 * np + 1], a[mi], bf[1], bf[3],
                                       acc16[mi][2 * np + 1][0], acc16[mi][2 * np + 1][1]);
                        }
                    }
                }
            }
        } else {
            // Odd stage: continue the chain, then promote into fp32 masters
            #pragma unroll
            for (int kc = 0; kc < 4; kc++) {
                uint32_t a[4][4];
                #pragma unroll
                for (int mi = 0; mi < 4; mi++)
                    ldmx4(a[mi], As + ((warp_m0 + mi * 16 + lrow16) * LDAh + kc * 16 + lcol8) * 2);
                #pragma unroll
                for (int np = 0; np < 4; np++) {
                    uint32_t bf[4];
                    ldmx4(bf, Bs + ((warp_n0 + np * 16 + lrow16) * LDAh + kc * 16 + lcol8) * 2);
                    #pragma unroll
                    for (int mi = 0; mi < 4; mi++) {
                        mma_f16acc(acc16[mi][2 * np + 0], a[mi], bf[0], bf[2],
                                   acc16[mi][2 * np + 0][0], acc16[mi][2 * np + 0][1]);
                        mma_f16acc(acc16[mi][2 * np + 1], a[mi], bf[1], bf[3],
                                   acc16[mi][2 * np + 1][0], acc16[mi][2 * np + 1][1]);
                    }
                }
            }
            #pragma unroll
            for (int mi = 0; mi < 4; mi++) {
                #pragma unroll
                for (int nj = 0; nj < 8; nj++) {
                    float2 f0 = __half22float2(*(__half2*)&acc16[mi][nj][0]);
                    float2 f1 = __half22float2(*(__half2*)&acc16[mi][nj][1]);
                    acc[mi][nj][0] += f0.x;
                    acc[mi][nj][1] += f0.y;
                    acc[mi][nj][2] += f1.x;
                    acc[mi][nj][3] += f1.y;
                }
            }
        }
    }

    const float QSC = 0.1803368801f;   // 0.125 * log2(e)
    #pragma unroll
    for (int mi = 0; mi < 4; mi++) {
        #pragma unroll
        for (int nj = 0; nj < 8; nj++) {
            int row0 = rowBase + warp_m0 + mi * 16 + g;
            int n = colBase + warp_n0 + nj * 8 + 2 * t4;
            int h = n / FDIM, f = n - h * FDIM;
            __half* dstbuf = (f < 64) ? g_k : ((f < 128) ? g_q : g_v);
            float sc = (f >= 64 && f < 128) ? QSC : 1.0f;
            int fd = f & 63;
            float2 bv = make_float2(bias[h * FDIM + f], bias[h * FDIM + f + 1]);
            #pragma unroll
            for (int half_ = 0; half_ < 2; half_++) {
                int r = row0 + half_ * 8;
                int b = r >> 11, ns = r & (SEQ - 1);
                __half2 ov = __floats2half2_rn((acc[mi][nj][half_ * 2 + 0] + bv.x) * sc,
                                               (acc[mi][nj][half_ * 2 + 1] + bv.y) * sc);
                *(__half2*)(dstbuf + (((size_t)(b * NHEAD + h)) * SEQ + ns) * HD + fd) = ov;
            }
        }
    }
}

// ---------------------------------------------------------------------------
// Causal flash attention fp16 (FA2) — byte-identical to R15/R16 (best).
// LPT-balanced schedule: 512 items (qt, bh); item j: qt = 15 - j/32, bh = j&31;
// grid 296 = 2/SM; CTA i runs item i, then item 591-i (valid i >= 80).
// Single-barrier double-buffer KV mainloop.
// ---------------------------------------------------------------------------
static constexpr int LDH = 72;                       // halves; 144 B rows
static constexpr int OFFQ = 0;
static constexpr int KVT_H = 64 * LDH;               // 4608 halves per K or V tile
static constexpr int OFFKV = 128 * LDH;
static constexpr int ATT_SMEM = (OFFKV + 4 * KVT_H) * 2;  // 55296 B
static constexpr int ATT_GRID = 296;                 // 2 x 148 SMs
static constexpr int NITEMS = 512;                   // 16 qt x 32 bh
static constexpr int PAIR_SUM = NITEMS - 1 + (ATT_GRID - (NITEMS - ATT_GRID));  // 591

__global__ __launch_bounds__(256, 2) void attn_fa_kernel(float* __restrict__ out)
{
    extern __shared__ __half sh[];
    const int tid = threadIdx.x, wid = tid >> 5, lane = tid & 31;
    const int t4 = lane & 3, g = lane >> 2;
    const int cta = blockIdx.x;                      // 0..295

    const uint32_t sb = smem_u32(sh);
    const int lrow16 = lane & 15;
    const int lcol8 = (lane >> 4) * 8;
    const int v_row = ((lane >> 4) << 3) + (lane & 7);
    const int v_col = ((lane >> 3) & 1) * 8;

    #pragma unroll 1
    for (int pass = 0; pass < 2; pass++) {
        const int j = pass ? (PAIR_SUM - cta) : cta;   // 591 - cta on pass 1
        if (j >= NITEMS) continue;     // pass 1 invalid for cta < 80

        const int qt = 15 - (j >> 5);
        const int bh = j & 31;
        const int qbase = qt * 128;

        const __half* Qg = g_q + (size_t)bh * SEQ * HD + (size_t)qbase * HD;
        const __half* Kg = g_k + (size_t)bh * SEQ * HD;
        const __half* Vg = g_v + (size_t)bh * SEQ * HD;

        auto load_kv = [&](int st, int jt) {
            uint32_t kb = sb + (OFFKV + st * 2 * KVT_H) * 2;
            const __half* kg = Kg + (size_t)jt * 64 * HD;
            const __half* vg = Vg + (size_t)jt * 64 * HD;
            #pragma unroll
            for (int q = 0; q < 2; q++) {
                int c = tid + q * 256;
                int row = c >> 3, ch = (c & 7) * 8;
                cp16(kb + (row * LDH + ch) * 2, kg + (size_t)row * HD + ch);
                cp16(kb + (KVT_H + row * LDH + ch) * 2, vg + (size_t)row * HD + ch);
            }
        };

        // Prologue: Q + KV tile 0; loop prefetches jt+1 after each top sync.
        #pragma unroll
        for (int q = 0; q < 4; q++) {
            int c = tid + q * 256;
            int row = c >> 3, ch = (c & 7) * 8;
            cp16(sb + (OFFQ + row * LDH + ch) * 2, Qg + (size_t)row * HD + ch);
        }
        load_kv(0, 0);
        cp_commit();
        cp_wait<0>();
        __syncthreads();

        uint32_t qf[4][4];
        #pragma unroll
        for (int kc = 0; kc < 4; kc++)
            ldmx4(qf[kc], sb + (OFFQ + (wid * 16 + lrow16) * LDH + kc * 16 + lcol8) * 2);

        float oacc[8][4];
        #pragma unroll
        for (int jj = 0; jj < 8; jj++)
            #pragma unroll
            for (int r = 0; r < 4; r++) oacc[jj][r] = 0.f;
        float mrow[2] = {-1e30f, -1e30f};
        float lrow[2] = {0.f, 0.f};

        const int wrmin = qbase + wid * 16;
        const int wrmax = wrmin + 15;
        const int ntiles = 2 * qt + 2;

        for (int jt = 0; jt < ntiles; jt++) {
            if (jt > 0) {
                cp_wait<0>();        // tile jt's load complete
                __syncthreads();     // all warps done with tile jt-1's buffer
            }
            if (jt + 1 < ntiles) {
                load_kv((jt + 1) & 1, jt + 1);
                cp_commit();
            }

            const int kb0 = jt * 64;
            uint32_t Ks = sb + (OFFKV + (jt & 1) * 2 * KVT_H) * 2;
            uint32_t Vs = Ks + KVT_H * 2;

            if (kb0 <= wrmax) {
                // ---- S = Q @ K^T (64 keys) ----
                float sacc[8][4];
                #pragma unroll
                for (int jj = 0; jj < 8; jj++)
                    #pragma unroll
                    for (int r = 0; r < 4; r++) sacc[jj][r] = 0.f;

                #pragma unroll
                for (int kc = 0; kc < 4; kc++) {
                    #pragma unroll
                    for (int np = 0; np < 4; np++) {
                        uint32_t bf[4];
                        ldmx4(bf, Ks + ((np * 16 + lrow16) * LDH + kc * 16 + lcol8) * 2);
                        mma_f16(sacc[2 * np + 0], qf[kc], bf[0], bf[2]);
                        mma_f16(sacc[2 * np + 1], qf[kc], bf[1], bf[3]);
                    }
                }

                // ---- causal mask (diagonal region only) ----
                if (kb0 + 63 > wrmin) {
                    #pragma unroll
                    for (int nf = 0; nf < 8; nf++) {
                        int key = kb0 + nf * 8 + 2 * t4;
                        #pragma unroll
                        for (int r = 0; r < 2; r++) {
                            int qrow = wrmin + r * 8 + g;
                            if (key > qrow)     sacc[nf][r * 2 + 0] = -1e30f;
                            if (key + 1 > qrow) sacc[nf][r * 2 + 1] = -1e30f;
                        }
                    }
                }

                // ---- rowmax (fp32) + alpha ----
                float alpha[2], mn2[2];
                #pragma unroll
                for (int r = 0; r < 2; r++) {
                    float mx = fmaxf(sacc[0][r * 2], sacc[0][r * 2 + 1]);
                    #pragma unroll
                    for (int nf = 1; nf < 8; nf++)
                        mx = fmaxf(mx, fmaxf(sacc[nf][r * 2], sacc[nf][r * 2 + 1]));
                    mx = fmaxf(mx, __shfl_xor_sync(0xffffffffu, mx, 1));
                    mx = fmaxf(mx, __shfl_xor_sync(0xffffffffu, mx, 2));
                    float mn = fmaxf(mrow[r], mx);
                    alpha[r] = ex2f(mrow[r] - mn);
                    mrow[r] = mn;
                    mn2[r] = mn;
                }

                // ---- exp in f16x2 (P born packed) ----
                __half2 ph2[8][2];
                #pragma unroll
                for (int nf = 0; nf < 8; nf++)
                    #pragma unroll
                    for (int r = 0; r < 2; r++)
                        ph2[nf][r] = h2ex2(__floats2half2_rn(sacc[nf][r * 2 + 0] - mn2[r],
                                                             sacc[nf][r * 2 + 1] - mn2[r]));

                // ---- row sum: hadd2 pairs then f32 ----
                #pragma unroll
                for (int r = 0; r < 2; r++) {
                    __half2 q01 = __hadd2(ph2[0][r], ph2[1][r]);
                    __half2 q23 = __hadd2(ph2[2][r], ph2[3][r]);
                    __half2 q45 = __hadd2(ph2[4][r], ph2[5][r]);
                    __half2 q67 = __hadd2(ph2[6][r], ph2[7][r]);
                    float2 f0 = __half22float2(q01);
                    float2 f1 = __half22float2(q23);
                    float2 f2 = __half22float2(q45);
                    float2 f3 = __half22float2(q67);
                    float rs = ((f0.x + f0.y) + (f1.x + f1.y)) + ((f2.x + f2.y) + (f3.x + f3.y));
                    rs += __shfl_xor_sync(0xffffffffu, rs, 1);
                    rs += __shfl_xor_sync(0xffffffffu, rs, 2);
                    lrow[r] = lrow[r] * alpha[r] + rs;
                }

                // ---- O rescale ----
                #pragma unroll
                for (int nf = 0; nf < 8; nf++) {
                    oacc[nf][0] *= alpha[0]; oacc[nf][1] *= alpha[0];
                    oacc[nf][2] *= alpha[1]; oacc[nf][3] *= alpha[1];
                }

                // ---- O += P @ V ----
                #pragma unroll
                for (int kc2 = 0; kc2 < 4; kc2++) {
                    uint32_t a[4] = {*(uint32_t*)&ph2[2 * kc2][0],     *(uint32_t*)&ph2[2 * kc2][1],
                                     *(uint32_t*)&ph2[2 * kc2 + 1][0], *(uint32_t*)&ph2[2 * kc2 + 1][1]};
                    #pragma unroll
                    for (int np = 0; np < 4; np++) {
                        uint32_t bf[4];
                        ldmx4t(bf, Vs + ((kc2 * 16 + v_row) * LDH + np * 16 + v_col) * 2);
                        mma_f16(oacc[2 * np + 0], a, bf[0], bf[2]);
                        mma_f16(oacc[2 * np + 1], a, bf[1], bf[3]);
                    }
                }
            }
        }

        // ---- epilogue for this item ----
        const int b = bh >> 4, h = bh & (NHEAD - 1);
        #pragma unroll
        for (int r = 0; r < 2; r++) {
            int qrow = qbase + wid * 16 + r * 8 + g;
            float inv = 1.0f / lrow[r];
            float* op = out + ((size_t)(b * SEQ + qrow)) * EMB + h * HD;
            #pragma unroll
            for (int nf = 0; nf < 8; nf++) {
                float2 ov = make_float2(oacc[nf][r * 2] * inv, oacc[nf][r * 2 + 1] * inv);
                *(float2*)(op + nf * 8 + 2 * t4) = ov;
            }
        }
        __syncthreads();   // all warps done with smem before next item reuses it
    }
}

// ---------------------------------------------------------------------------
// Host launcher
// ---------------------------------------------------------------------------
extern "C" void kernel_launch(void* const* d_in, const int* in_sizes, int n_in,
                              void* d_out, int out_size)
{
    const float* x    = (const float*)d_in[0];  // [2,2048,1024]
    const float* W    = (const float*)d_in[1];  // [16,1024,192]
    const float* bias = (const float*)d_in[2];  // [16,192]
    float* out = (float*)d_out;                 // [2,2048,1024]

    prep_kernel<<<4096 + 3072, 256>>>((const float4*)x, W);

    static bool smem_set = false;
    if (!smem_set) {
        cudaFuncSetAttribute(qkv_mma_kernel, cudaFuncAttributeMaxDynamicSharedMemorySize, QKV_SMEM);
        cudaFuncSetAttribute(attn_fa_kernel, cudaFuncAttributeMaxDynamicSharedMemorySize, ATT_SMEM);
        smem_set = true;
    }
    qkv_mma_kernel<<<dim3(ROWS / CTA_M, NTOT / CTA_N), 128, QKV_SMEM>>>(bias);

    attn_fa_kernel<<<ATT_GRID, 256, ATT_SMEM>>>(out);
}